// round 8
// baseline (speedup 1.0000x reference)
#include <cuda_runtime.h>
#include <cuda_bf16.h>
#include <math.h>
#include <stdint.h>

// Problem constants
#define BB   2
#define SS   2048
#define DDIM 2048
#define HH   16
#define HDIM 128
#define FFD  5632
#define BSR  (BB * SS)          // 4096 rows total
#define EPSV 1e-5f

// ---------------------------------------------------------------------------
// Scratch (static device globals — no allocations allowed)
// ---------------------------------------------------------------------------
__device__ float g_h1[BSR * FFD];
__device__ float g_h3[BSR * FFD];
__device__ float g_ff[BSR * DDIM];

__device__ __nv_bfloat16 g_xn_h[BSR * DDIM], g_xn_l[BSR * DDIM];
__device__ __nv_bfloat16 g_yn_h[BSR * DDIM], g_yn_l[BSR * DDIM];
__device__ __nv_bfloat16 g_q_h [BSR * DDIM], g_q_l [BSR * DDIM];
__device__ __nv_bfloat16 g_k_h [BSR * DDIM], g_k_l [BSR * DDIM];
__device__ __nv_bfloat16 g_v_h [BSR * DDIM], g_v_l [BSR * DDIM];
__device__ __nv_bfloat16 g_att_h[BSR * DDIM], g_att_l[BSR * DDIM];
__device__ __nv_bfloat16 g_pr_h[BSR * DDIM], g_pr_l[BSR * DDIM];
__device__ __nv_bfloat16 g_hs_h[BSR * FFD],  g_hs_l[BSR * FFD];
__device__ __nv_bfloat16 g_w_h [FFD * DDIM], g_w_l [FFD * DDIM];

// ---------------------------------------------------------------------------
// Helpers (baseline PTX only — build targets compute_103)
// ---------------------------------------------------------------------------
__device__ __forceinline__ void mma_bf16(float* d, const uint32_t* a, const uint32_t* b) {
    asm volatile(
        "mma.sync.aligned.m16n8k16.row.col.f32.bf16.bf16.f32 "
        "{%0,%1,%2,%3}, {%4,%5,%6,%7}, {%8,%9}, {%0,%1,%2,%3};"
        : "+f"(d[0]), "+f"(d[1]), "+f"(d[2]), "+f"(d[3])
        : "r"(a[0]), "r"(a[1]), "r"(a[2]), "r"(a[3]), "r"(b[0]), "r"(b[1]));
}

// pack two fp32 -> bf16x2 (lo = first element, per little-endian frag layout)
__device__ __forceinline__ uint32_t cvt_bf16x2(float hi, float lo) {
    uint32_t r;
    asm("cvt.rn.bf16x2.f32 %0, %1, %2;" : "=r"(r) : "f"(hi), "f"(lo));
    return r;
}
__device__ __forceinline__ float un_lo(uint32_t u) { return __uint_as_float(u << 16); }
__device__ __forceinline__ float un_hi(uint32_t u) { return __uint_as_float(u & 0xffff0000u); }

// Swizzled LDS.32 from a tile with 128B rows (XOR-16B swizzle)
__device__ __forceinline__ uint32_t lds_sw(const char* base, int row, int kbyte) {
    uint32_t cb = (uint32_t)kbyte ^ (((uint32_t)row & 7u) << 4);
    return *(const uint32_t*)(base + row * 128 + cb);
}
// Swizzled LDS.32 from a tile with 256B rows (Q/K tiles in flash)
__device__ __forceinline__ uint32_t ld_qk(const char* base, int row, int kbyte) {
    uint32_t cb = (uint32_t)kbyte ^ (((uint32_t)row & 7u) << 4);
    return *(const uint32_t*)(base + row * 256 + cb);
}
// Swizzled LDS.32 from transposed-V tile [128 hd][64 kv] (128B rows).
// Swizzle mixes hd bits 0-2 and 3-5 so BOTH the kv-major store and the
// hd-spread fragment load are (near) conflict-free.
__device__ __forceinline__ uint32_t vt_sw(int hd) {
    return ((((uint32_t)hd & 7u) ^ (((uint32_t)hd >> 3) & 7u)) << 4);
}
__device__ __forceinline__ uint32_t ld_vt(const char* base, int hd, int kbyte) {
    return *(const uint32_t*)(base + hd * 128 + ((uint32_t)kbyte ^ vt_sw(hd)));
}

// ---------------------------------------------------------------------------
// fp32 -> bf16 hi/lo split (weights only now)
// ---------------------------------------------------------------------------
__global__ __launch_bounds__(256) void split_bf16_kernel(
    const float* __restrict__ in, __nv_bfloat16* __restrict__ hi,
    __nv_bfloat16* __restrict__ lo, int n4)
{
    const int i = blockIdx.x * 256 + threadIdx.x;
    if (i >= n4) return;
    float4 v = ((const float4*)in)[i];
    uint32_t h0 = cvt_bf16x2(v.y, v.x);
    uint32_t h1 = cvt_bf16x2(v.w, v.z);
    uint32_t l0 = cvt_bf16x2(v.y - un_hi(h0), v.x - un_lo(h0));
    uint32_t l1 = cvt_bf16x2(v.w - un_hi(h1), v.z - un_lo(h1));
    ((uint2*)hi)[i] = make_uint2(h0, h1);
    ((uint2*)lo)[i] = make_uint2(l0, l1);
}

// ---------------------------------------------------------------------------
// bf16x3 GEMM (mma.sync): C[M,N] = A[M,K] @ B[N,K]^T, fp32 accumulate.
// C += Ah*Bh + Ah*Bl + Al*Bh.  Tile 128x128, Kc=64 (128B rows), double buffer.
// Phase-major MMA order (reuse distance 32) to avoid RAW-latency serialization.
// Epilogue: if Ch != nullptr, write bf16 hi/lo split; else fp32.
// ---------------------------------------------------------------------------
#define GEMM_TILE_BYTES 16384
#define GEMM_BUF_BYTES  (4 * GEMM_TILE_BYTES)
#define GEMM_SMEM       (2 * GEMM_BUF_BYTES + 1024)

__global__ __launch_bounds__(128, 1)
void gemm_bf16x3(const __nv_bfloat16* __restrict__ Ah, const __nv_bfloat16* __restrict__ Al,
                 const __nv_bfloat16* __restrict__ Bh, const __nv_bfloat16* __restrict__ Bl,
                 float* __restrict__ C,
                 __nv_bfloat16* __restrict__ Ch, __nv_bfloat16* __restrict__ Cl,
                 int M, int N, int K)
{
    extern __shared__ char dyn[];
    const int tid  = threadIdx.x;
    const int wid  = tid >> 5;
    const int lane = tid & 31;
    const int bm   = blockIdx.y * 128;
    const int bn   = blockIdx.x * 128;

    uint32_t dyn_u;
    asm("{ .reg .u64 t; cvta.to.shared.u64 t, %1; cvt.u32.u64 %0, t; }" : "=r"(dyn_u) : "l"(dyn));
    char* tile_p = dyn + (((dyn_u + 1023u) & ~1023u) - dyn_u);

    const int nk = K >> 6;
    const __nv_bfloat16* pAh = Ah + (size_t)(bm + tid) * K;
    const __nv_bfloat16* pAl = Al + (size_t)(bm + tid) * K;
    const __nv_bfloat16* pBh = Bh + (size_t)(bn + tid) * K;
    const __nv_bfloat16* pBl = Bl + (size_t)(bn + tid) * K;

    float acc[2][16][4];
#pragma unroll
    for (int mi = 0; mi < 2; mi++)
#pragma unroll
        for (int j = 0; j < 16; j++)
#pragma unroll
            for (int q = 0; q < 4; q++) acc[mi][j][q] = 0.f;

    const int lr = lane >> 2;
    const int lc = (lane & 3) << 2;

    for (int i = 0; i < nk; i++) {
        const int b = i & 1;
        __syncthreads();
        {
            const int k0 = i << 6;
            char* bufA_h = tile_p + b * GEMM_BUF_BYTES;
            char* bufA_l = bufA_h + GEMM_TILE_BYTES;
            char* bufB_h = bufA_l + GEMM_TILE_BYTES;
            char* bufB_l = bufB_h + GEMM_TILE_BYTES;
            const uint4* sAh = (const uint4*)(pAh + k0);
            const uint4* sAl = (const uint4*)(pAl + k0);
            const uint4* sBh = (const uint4*)(pBh + k0);
            const uint4* sBl = (const uint4*)(pBl + k0);
#pragma unroll
            for (int j = 0; j < 8; j++) {
                uint32_t off = (uint32_t)(tid * 128 + j * 16);
                uint32_t sw  = off ^ ((off >> 3) & 0x70u);
                *(uint4*)(bufA_h + sw) = sAh[j];
                *(uint4*)(bufA_l + sw) = sAl[j];
                *(uint4*)(bufB_h + sw) = sBh[j];
                *(uint4*)(bufB_l + sw) = sBl[j];
            }
        }
        __syncthreads();

        const char* bAh = tile_p + b * GEMM_BUF_BYTES;
        const char* bAl = bAh + GEMM_TILE_BYTES;
        const char* bBh = bAl + GEMM_TILE_BYTES;
        const char* bBl = bBh + GEMM_TILE_BYTES;

#pragma unroll
        for (int ks = 0; ks < 4; ks++) {
            const int kb = ks * 32 + lc;
            uint32_t ah[2][4], al2[2][4];
#pragma unroll
            for (int mi = 0; mi < 2; mi++) {
                const int r0 = wid * 32 + mi * 16 + lr;
                ah[mi][0]  = lds_sw(bAh, r0,     kb);
                ah[mi][1]  = lds_sw(bAh, r0 + 8, kb);
                ah[mi][2]  = lds_sw(bAh, r0,     kb + 16);
                ah[mi][3]  = lds_sw(bAh, r0 + 8, kb + 16);
                al2[mi][0] = lds_sw(bAl, r0,     kb);
                al2[mi][1] = lds_sw(bAl, r0 + 8, kb);
                al2[mi][2] = lds_sw(bAl, r0,     kb + 16);
                al2[mi][3] = lds_sw(bAl, r0 + 8, kb + 16);
            }
            // phase 0: Ah * Bh
#pragma unroll
            for (int j = 0; j < 16; j++) {
                const int n0 = j * 8 + lr;
                uint32_t bb[2];
                bb[0] = lds_sw(bBh, n0, kb);
                bb[1] = lds_sw(bBh, n0, kb + 16);
                mma_bf16(acc[0][j], ah[0], bb);
                mma_bf16(acc[1][j], ah[1], bb);
            }
            // phase 1: Ah * Bl
#pragma unroll
            for (int j = 0; j < 16; j++) {
                const int n0 = j * 8 + lr;
                uint32_t bb[2];
                bb[0] = lds_sw(bBl, n0, kb);
                bb[1] = lds_sw(bBl, n0, kb + 16);
                mma_bf16(acc[0][j], ah[0], bb);
                mma_bf16(acc[1][j], ah[1], bb);
            }
            // phase 2: Al * Bh
#pragma unroll
            for (int j = 0; j < 16; j++) {
                const int n0 = j * 8 + lr;
                uint32_t bb[2];
                bb[0] = lds_sw(bBh, n0, kb);
                bb[1] = lds_sw(bBh, n0, kb + 16);
                mma_bf16(acc[0][j], al2[0], bb);
                mma_bf16(acc[1][j], al2[1], bb);
            }
        }
    }

    if (Ch) {
#pragma unroll
        for (int mi = 0; mi < 2; mi++) {
            const int r0 = bm + wid * 32 + mi * 16 + lr;
#pragma unroll
            for (int j = 0; j < 16; j++) {
                const int col = bn + j * 8 + ((lane & 3) << 1);
                uint32_t h0 = cvt_bf16x2(acc[mi][j][1], acc[mi][j][0]);
                uint32_t l0 = cvt_bf16x2(acc[mi][j][1] - un_hi(h0), acc[mi][j][0] - un_lo(h0));
                uint32_t h1 = cvt_bf16x2(acc[mi][j][3], acc[mi][j][2]);
                uint32_t l1 = cvt_bf16x2(acc[mi][j][3] - un_hi(h1), acc[mi][j][2] - un_lo(h1));
                *(uint32_t*)(Ch + (size_t)r0 * N + col)       = h0;
                *(uint32_t*)(Cl + (size_t)r0 * N + col)       = l0;
                *(uint32_t*)(Ch + (size_t)(r0 + 8) * N + col) = h1;
                *(uint32_t*)(Cl + (size_t)(r0 + 8) * N + col) = l1;
            }
        }
    } else {
#pragma unroll
        for (int mi = 0; mi < 2; mi++) {
            const int r0 = bm + wid * 32 + mi * 16 + lr;
#pragma unroll
            for (int j = 0; j < 16; j++) {
                const int col = bn + j * 8 + ((lane & 3) << 1);
                *(float2*)(C + (size_t)r0 * N + col)       = make_float2(acc[mi][j][0], acc[mi][j][1]);
                *(float2*)(C + (size_t)(r0 + 8) * N + col) = make_float2(acc[mi][j][2], acc[mi][j][3]);
            }
        }
    }
}

// ---------------------------------------------------------------------------
// Flash attention, tensor-core bf16x3 (mma.sync).
// Inputs: Q/K/V as bf16 hi/lo pairs, row-major (BSR, DDIM), head h at cols
// [h*128,(h+1)*128). Output: att as bf16 hi/lo.
// Block = 64 q-rows of one (b,h); 4 warps x 16 q-rows; 32 kv tiles of 64.
// SMEM: Qh,Ql,Kh,Kl [64][256B] + VtH,VtL [128][128B] = 96KB dynamic.
// ---------------------------------------------------------------------------
#define FL_SMEM (6 * 16384)

__global__ __launch_bounds__(128) void flash_bf16_kernel(
    const __nv_bfloat16* __restrict__ Qh_g, const __nv_bfloat16* __restrict__ Ql_g,
    const __nv_bfloat16* __restrict__ Kh_g, const __nv_bfloat16* __restrict__ Kl_g,
    const __nv_bfloat16* __restrict__ Vh_g, const __nv_bfloat16* __restrict__ Vl_g,
    __nv_bfloat16* __restrict__ Oh_g, __nv_bfloat16* __restrict__ Ol_g)
{
    extern __shared__ char sm[];
    char* sQh = sm;
    char* sQl = sm + 16384;
    char* sKh = sm + 2 * 16384;
    char* sKl = sm + 3 * 16384;
    char* sVh = sm + 4 * 16384;   // transposed: [128 hd][64 kv]
    char* sVl = sm + 5 * 16384;

    const int tid  = threadIdx.x;
    const int wid  = tid >> 5;
    const int lane = tid & 31;
    const int lr   = lane >> 2;
    const int c0   = lane & 3;
    const int q0   = blockIdx.x * 64;
    const int h    = blockIdx.y;
    const int b    = blockIdx.z;
    const size_t rowbase = (size_t)b * SS;
    const float scale = 0.0883883476483184405f;   // 1/sqrt(128)

    // ---- load Q tile (hi/lo), 64 rows x 256B, swizzled ----
    {
        const char* qh = (const char*)(Qh_g + (rowbase + q0) * DDIM + h * HDIM);
        const char* ql = (const char*)(Ql_g + (rowbase + q0) * DDIM + h * HDIM);
#pragma unroll
        for (int it = 0; it < 8; it++) {
            int li = tid + it * 128;
            int r = li >> 4, c = (li & 15) * 16;
            uint32_t sw = (uint32_t)c ^ (((uint32_t)r & 7u) << 4);
            *(uint4*)(sQh + r * 256 + sw) = *(const uint4*)(qh + (size_t)r * (DDIM * 2) + c);
            *(uint4*)(sQl + r * 256 + sw) = *(const uint4*)(ql + (size_t)r * (DDIM * 2) + c);
        }
    }

    float o[16][4];
#pragma unroll
    for (int j = 0; j < 16; j++)
#pragma unroll
        for (int q = 0; q < 4; q++) o[j][q] = 0.f;
    float m0 = -1e30f, m1 = -1e30f, l0 = 0.f, l1 = 0.f;

    const int r0w = wid * 16 + lr;

    for (int t = 0; t < SS / 64; t++) {
        __syncthreads();   // previous tile fully consumed (also orders Q store on t=0)
        {
            const char* kh = (const char*)(Kh_g + (rowbase + t * 64) * DDIM + h * HDIM);
            const char* kl = (const char*)(Kl_g + (rowbase + t * 64) * DDIM + h * HDIM);
            const char* vh = (const char*)(Vh_g + (rowbase + t * 64) * DDIM + h * HDIM);
            const char* vl = (const char*)(Vl_g + (rowbase + t * 64) * DDIM + h * HDIM);
#pragma unroll
            for (int it = 0; it < 8; it++) {
                int li = tid + it * 128;
                int r = li >> 4, c = (li & 15) * 16;
                uint32_t sw = (uint32_t)c ^ (((uint32_t)r & 7u) << 4);
                *(uint4*)(sKh + r * 256 + sw) = *(const uint4*)(kh + (size_t)r * (DDIM * 2) + c);
                *(uint4*)(sKl + r * 256 + sw) = *(const uint4*)(kl + (size_t)r * (DDIM * 2) + c);
                // V: load 8 bf16 (hd c/2 .. c/2+7 of kv row r), transpose-scatter
                uint4 dh = *(const uint4*)(vh + (size_t)r * (DDIM * 2) + c);
                uint4 dl = *(const uint4*)(vl + (size_t)r * (DDIM * 2) + c);
                const uint16_t* ph  = (const uint16_t*)&dh;
                const uint16_t* pl6 = (const uint16_t*)&dl;
                int hd0 = c >> 1;
#pragma unroll
                for (int e = 0; e < 8; e++) {
                    int hd = hd0 + e;
                    uint32_t kvb = ((uint32_t)(r * 2)) ^ vt_sw(hd);
                    *(uint16_t*)(sVh + hd * 128 + kvb) = ph[e];
                    *(uint16_t*)(sVl + hd * 128 + kvb) = pl6[e];
                }
            }
        }
        __syncthreads();

        // ---- scores S = Q K^T (bf16x3): warp rows {r0w, r0w+8}, 64 kv cols ----
        float s[8][4];
#pragma unroll
        for (int j = 0; j < 8; j++)
#pragma unroll
            for (int q = 0; q < 4; q++) s[j][q] = 0.f;

#pragma unroll
        for (int phase = 0; phase < 3; phase++) {
            const char* qb = (phase == 2) ? sQl : sQh;
            const char* kb = (phase == 1) ? sKl : sKh;
#pragma unroll
            for (int ks = 0; ks < 8; ks++) {
                const int kbq = ks * 32 + c0 * 4;
                uint32_t qa[4];
                qa[0] = ld_qk(qb, r0w,     kbq);
                qa[1] = ld_qk(qb, r0w + 8, kbq);
                qa[2] = ld_qk(qb, r0w,     kbq + 16);
                qa[3] = ld_qk(qb, r0w + 8, kbq + 16);
#pragma unroll
                for (int j = 0; j < 8; j++) {
                    const int n0 = j * 8 + lr;
                    uint32_t bb[2];
                    bb[0] = ld_qk(kb, n0, kbq);
                    bb[1] = ld_qk(kb, n0, kbq + 16);
                    mma_bf16(s[j], qa, bb);
                }
            }
        }

        // ---- online softmax (rows r0w and r0w+8) ----
        float mx0 = -1e30f, mx1 = -1e30f;
#pragma unroll
        for (int j = 0; j < 8; j++) {
            s[j][0] *= scale; s[j][1] *= scale; s[j][2] *= scale; s[j][3] *= scale;
            mx0 = fmaxf(mx0, fmaxf(s[j][0], s[j][1]));
            mx1 = fmaxf(mx1, fmaxf(s[j][2], s[j][3]));
        }
        mx0 = fmaxf(mx0, __shfl_xor_sync(0xffffffffu, mx0, 1));
        mx0 = fmaxf(mx0, __shfl_xor_sync(0xffffffffu, mx0, 2));
        mx1 = fmaxf(mx1, __shfl_xor_sync(0xffffffffu, mx1, 1));
        mx1 = fmaxf(mx1, __shfl_xor_sync(0xffffffffu, mx1, 2));
        const float mn0 = fmaxf(m0, mx0), mn1 = fmaxf(m1, mx1);
        const float al0 = __expf(m0 - mn0), al1 = __expf(m1 - mn1);

        uint32_t pah[4][4], pal[4][4];
        float rs0 = 0.f, rs1 = 0.f;
#pragma unroll
        for (int j = 0; j < 8; j++) {
            float p0 = __expf(s[j][0] - mn0);
            float p1 = __expf(s[j][1] - mn0);
            float p2 = __expf(s[j][2] - mn1);
            float p3 = __expf(s[j][3] - mn1);
            rs0 += p0 + p1; rs1 += p2 + p3;
            uint32_t h01 = cvt_bf16x2(p1, p0);
            uint32_t h23 = cvt_bf16x2(p3, p2);
            uint32_t q01 = cvt_bf16x2(p1 - un_hi(h01), p0 - un_lo(h01));
            uint32_t q23 = cvt_bf16x2(p3 - un_hi(h23), p2 - un_lo(h23));
            const int kvks = j >> 1, half = (j & 1) << 1;
            pah[kvks][half]     = h01;   // a0/a2 (row lr)
            pah[kvks][half + 1] = h23;   // a1/a3 (row lr+8)
            pal[kvks][half]     = q01;
            pal[kvks][half + 1] = q23;
        }
        rs0 += __shfl_xor_sync(0xffffffffu, rs0, 1);
        rs0 += __shfl_xor_sync(0xffffffffu, rs0, 2);
        rs1 += __shfl_xor_sync(0xffffffffu, rs1, 1);
        rs1 += __shfl_xor_sync(0xffffffffu, rs1, 2);
        l0 = l0 * al0 + rs0;
        l1 = l1 * al1 + rs1;
        m0 = mn0; m1 = mn1;
#pragma unroll
        for (int jn = 0; jn < 16; jn++) {
            o[jn][0] *= al0; o[jn][1] *= al0;
            o[jn][2] *= al1; o[jn][3] *= al1;
        }

        // ---- O += P V (bf16x3): Ph*Vh + Ph*Vl + Pl*Vh ----
#pragma unroll
        for (int phase = 0; phase < 3; phase++) {
            const char* vb = (phase == 1) ? sVl : sVh;
#pragma unroll
            for (int kvks = 0; kvks < 4; kvks++) {
                const uint32_t* pa = (phase == 2) ? pal[kvks] : pah[kvks];
                const int kb = kvks * 32 + c0 * 4;
#pragma unroll
                for (int jn = 0; jn < 16; jn++) {
                    const int n0 = jn * 8 + lr;
                    uint32_t bb[2];
                    bb[0] = ld_vt(vb, n0, kb);
                    bb[1] = ld_vt(vb, n0, kb + 16);
                    mma_bf16(o[jn], pa, bb);
                }
            }
        }
    }

    // ---- normalize and store att as bf16 hi/lo ----
    const float i0 = 1.f / l0, i1 = 1.f / l1;
    const size_t rg0 = rowbase + q0 + r0w;
    const int colb = h * HDIM + (c0 << 1);
#pragma unroll
    for (int jn = 0; jn < 16; jn++) {
        float v0 = o[jn][0] * i0, v1 = o[jn][1] * i0;
        float v2 = o[jn][2] * i1, v3 = o[jn][3] * i1;
        uint32_t h01 = cvt_bf16x2(v1, v0);
        uint32_t l01 = cvt_bf16x2(v1 - un_hi(h01), v0 - un_lo(h01));
        uint32_t h23 = cvt_bf16x2(v3, v2);
        uint32_t l23 = cvt_bf16x2(v3 - un_hi(h23), v2 - un_lo(h23));
        const size_t off0 = rg0 * DDIM + colb + jn * 8;
        const size_t off1 = (rg0 + 8) * DDIM + colb + jn * 8;
        *(uint32_t*)(Oh_g + off0) = h01;
        *(uint32_t*)(Ol_g + off0) = l01;
        *(uint32_t*)(Oh_g + off1) = h23;
        *(uint32_t*)(Ol_g + off1) = l23;
    }
}

// ---------------------------------------------------------------------------
// RMSNorm with fused bf16 hi/lo split output
// ---------------------------------------------------------------------------
__global__ __launch_bounds__(256) void rmsnorm_split_kernel(
    const float* __restrict__ in, const float* __restrict__ w,
    __nv_bfloat16* __restrict__ oh, __nv_bfloat16* __restrict__ ol)
{
    const int row  = blockIdx.x;
    const int base = threadIdx.x * 8;
    const float* r = in + (size_t)row * DDIM;

    float v[8];
    *(float4*)(v)     = *(const float4*)(r + base);
    *(float4*)(v + 4) = *(const float4*)(r + base + 4);

    float ss = 0.f;
#pragma unroll
    for (int i = 0; i < 8; i++) ss += v[i] * v[i];
#pragma unroll
    for (int o = 16; o > 0; o >>= 1) ss += __shfl_xor_sync(0xffffffffu, ss, o);

    __shared__ float red[8];
    __shared__ float sscale;
    if ((threadIdx.x & 31) == 0) red[threadIdx.x >> 5] = ss;
    __syncthreads();
    if (threadIdx.x == 0) {
        float t = 0.f;
#pragma unroll
        for (int i = 0; i < 8; i++) t += red[i];
        sscale = rsqrtf(t / (float)DDIM + EPSV);
    }
    __syncthreads();
    const float sc = sscale;

    uint32_t hh[4], ll[4];
#pragma unroll
    for (int p = 0; p < 4; p++) {
        float f0 = v[2 * p]     * sc * w[base + 2 * p];
        float f1 = v[2 * p + 1] * sc * w[base + 2 * p + 1];
        hh[p] = cvt_bf16x2(f1, f0);
        ll[p] = cvt_bf16x2(f1 - un_hi(hh[p]), f0 - un_lo(hh[p]));
    }
    *(uint4*)(oh + (size_t)row * DDIM + base) = make_uint4(hh[0], hh[1], hh[2], hh[3]);
    *(uint4*)(ol + (size_t)row * DDIM + base) = make_uint4(ll[0], ll[1], ll[2], ll[3]);
}

// ---------------------------------------------------------------------------
// RMSNorm of (ff + residual) -> final fp32 output
// ---------------------------------------------------------------------------
__global__ __launch_bounds__(256) void rms_resid_out_kernel(
    const float* __restrict__ ff, const float* __restrict__ res,
    const float* __restrict__ w, float* __restrict__ out)
{
    const int row  = blockIdx.x;
    const int base = threadIdx.x * 8;
    const float* f = ff  + (size_t)row * DDIM;
    const float* r = res + (size_t)row * DDIM;

    float4 a0 = *(const float4*)(f + base);
    float4 a1 = *(const float4*)(f + base + 4);
    float4 b0 = *(const float4*)(r + base);
    float4 b1 = *(const float4*)(r + base + 4);

    float v[8];
    v[0] = a0.x + b0.x; v[1] = a0.y + b0.y; v[2] = a0.z + b0.z; v[3] = a0.w + b0.w;
    v[4] = a1.x + b1.x; v[5] = a1.y + b1.y; v[6] = a1.z + b1.z; v[7] = a1.w + b1.w;

    float ss = 0.f;
#pragma unroll
    for (int i = 0; i < 8; i++) ss += v[i] * v[i];
#pragma unroll
    for (int o = 16; o > 0; o >>= 1) ss += __shfl_xor_sync(0xffffffffu, ss, o);

    __shared__ float red[8];
    __shared__ float sscale;
    if ((threadIdx.x & 31) == 0) red[threadIdx.x >> 5] = ss;
    __syncthreads();
    if (threadIdx.x == 0) {
        float t = 0.f;
#pragma unroll
        for (int i = 0; i < 8; i++) t += red[i];
        sscale = rsqrtf(t / (float)DDIM + EPSV);
    }
    __syncthreads();
    const float sc = sscale;

    float o8[8];
#pragma unroll
    for (int i = 0; i < 8; i++) o8[i] = v[i] * sc * w[base + i];
    float* op = out + (size_t)row * DDIM + base;
    *(float4*)(op)     = *(float4*)(o8);
    *(float4*)(op + 4) = *(float4*)(o8 + 4);
}

// ---------------------------------------------------------------------------
// SiLU-mul with fused bf16 hi/lo split output: hs = silu(h1) * h3
// ---------------------------------------------------------------------------
__global__ __launch_bounds__(256) void silu_mul_split_kernel(
    const float* __restrict__ h1, const float* __restrict__ h3,
    __nv_bfloat16* __restrict__ oh, __nv_bfloat16* __restrict__ ol, int n4)
{
    const int i = blockIdx.x * 256 + threadIdx.x;
    if (i >= n4) return;
    float4 a = ((const float4*)h1)[i];
    float4 b = ((const float4*)h3)[i];
    float r0 = a.x * (1.f / (1.f + __expf(-a.x))) * b.x;
    float r1 = a.y * (1.f / (1.f + __expf(-a.y))) * b.y;
    float r2 = a.z * (1.f / (1.f + __expf(-a.z))) * b.z;
    float r3 = a.w * (1.f / (1.f + __expf(-a.w))) * b.w;
    uint32_t h0 = cvt_bf16x2(r1, r0);
    uint32_t h1u = cvt_bf16x2(r3, r2);
    uint32_t l0 = cvt_bf16x2(r1 - un_hi(h0), r0 - un_lo(h0));
    uint32_t l1 = cvt_bf16x2(r3 - un_hi(h1u), r2 - un_lo(h1u));
    ((uint2*)oh)[i] = make_uint2(h0, h1u);
    ((uint2*)ol)[i] = make_uint2(l0, l1);
}

// ---------------------------------------------------------------------------
// Host orchestration
// ---------------------------------------------------------------------------
extern "C" void kernel_launch(void* const* d_in, const int* in_sizes, int n_in,
                              void* d_out, int out_size)
{
    (void)in_sizes; (void)n_in; (void)out_size;

    const float* x           = (const float*)d_in[0];
    const float* y           = (const float*)d_in[1];
    const float* attn_norm_w = (const float*)d_in[2];
    const float* wq[2]  = {(const float*)d_in[3],  (const float*)d_in[7]};
    const float* wk[2]  = {(const float*)d_in[4],  (const float*)d_in[8]};
    const float* wv[2]  = {(const float*)d_in[5],  (const float*)d_in[9]};
    const float* wo[2]  = {(const float*)d_in[6],  (const float*)d_in[10]};
    const float* w1[2]  = {(const float*)d_in[11], (const float*)d_in[15]};
    const float* w2[2]  = {(const float*)d_in[12], (const float*)d_in[16]};
    const float* w3[2]  = {(const float*)d_in[13], (const float*)d_in[17]};
    const float* fnw[2] = {(const float*)d_in[14], (const float*)d_in[18]};
    float* out = (float*)d_out;

    float *h1, *h3, *ff;
    cudaGetSymbolAddress((void**)&h1, g_h1);
    cudaGetSymbolAddress((void**)&h3, g_h3);
    cudaGetSymbolAddress((void**)&ff, g_ff);

    __nv_bfloat16 *xnh, *xnl, *ynh, *ynl, *qh, *ql, *kh, *kl, *vh, *vl;
    __nv_bfloat16 *ath, *atl, *prh, *prl, *hsh, *hsl, *wh, *wl;
    cudaGetSymbolAddress((void**)&xnh, g_xn_h); cudaGetSymbolAddress((void**)&xnl, g_xn_l);
    cudaGetSymbolAddress((void**)&ynh, g_yn_h); cudaGetSymbolAddress((void**)&ynl, g_yn_l);
    cudaGetSymbolAddress((void**)&qh,  g_q_h);  cudaGetSymbolAddress((void**)&ql,  g_q_l);
    cudaGetSymbolAddress((void**)&kh,  g_k_h);  cudaGetSymbolAddress((void**)&kl,  g_k_l);
    cudaGetSymbolAddress((void**)&vh,  g_v_h);  cudaGetSymbolAddress((void**)&vl,  g_v_l);
    cudaGetSymbolAddress((void**)&ath, g_att_h); cudaGetSymbolAddress((void**)&atl, g_att_l);
    cudaGetSymbolAddress((void**)&prh, g_pr_h); cudaGetSymbolAddress((void**)&prl, g_pr_l);
    cudaGetSymbolAddress((void**)&hsh, g_hs_h); cudaGetSymbolAddress((void**)&hsl, g_hs_l);
    cudaGetSymbolAddress((void**)&wh,  g_w_h);  cudaGetSymbolAddress((void**)&wl,  g_w_l);

    cudaFuncSetAttribute(gemm_bf16x3,
                         cudaFuncAttributeMaxDynamicSharedMemorySize, GEMM_SMEM);
    cudaFuncSetAttribute(flash_bf16_kernel,
                         cudaFuncAttributeMaxDynamicSharedMemorySize, FL_SMEM);

    // Pre-norms with fused hi/lo split
    rmsnorm_split_kernel<<<BSR, 256>>>(x, attn_norm_w, xnh, xnl);
    rmsnorm_split_kernel<<<BSR, 256>>>(y, attn_norm_w, ynh, ynl);

    const dim3 gAttn(SS / 64, HH, BB);
    const int  n4ff = BSR * FFD / 4;

    auto splitw = [&](const float* src, int n) {
        int n4s = n / 4;
        split_bf16_kernel<<<(n4s + 255) / 256, 256>>>(src, wh, wl, n4s);
    };
    auto gemm_s = [&](const __nv_bfloat16* Ah_, const __nv_bfloat16* Al_,
                      __nv_bfloat16* Ch_, __nv_bfloat16* Cl_, int M, int N, int K) {
        dim3 g(N / 128, M / 128);
        gemm_bf16x3<<<g, 128, GEMM_SMEM>>>(Ah_, Al_, wh, wl, nullptr, Ch_, Cl_, M, N, K);
    };
    auto gemm_f = [&](const __nv_bfloat16* Ah_, const __nv_bfloat16* Al_,
                      float* C_, int M, int N, int K) {
        dim3 g(N / 128, M / 128);
        gemm_bf16x3<<<g, 128, GEMM_SMEM>>>(Ah_, Al_, wh, wl, C_, nullptr, nullptr, M, N, K);
    };

    for (int p = 0; p < 2; p++) {
        const __nv_bfloat16* qih = (p == 0) ? xnh : ynh;
        const __nv_bfloat16* qil = (p == 0) ? xnl : ynl;
        const __nv_bfloat16* kih = (p == 0) ? ynh : xnh;
        const __nv_bfloat16* kil = (p == 0) ? ynl : xnl;
        const float* resid = (p == 0) ? x : y;

        splitw(wq[p], DDIM * DDIM);  gemm_s(qih, qil, qh, ql, BSR, DDIM, DDIM);
        splitw(wk[p], DDIM * DDIM);  gemm_s(kih, kil, kh, kl, BSR, DDIM, DDIM);
        splitw(wv[p], DDIM * DDIM);  gemm_s(kih, kil, vh, vl, BSR, DDIM, DDIM);

        flash_bf16_kernel<<<gAttn, 128, FL_SMEM>>>(qh, ql, kh, kl, vh, vl, ath, atl);

        splitw(wo[p], DDIM * DDIM);  gemm_s(ath, atl, prh, prl, BSR, DDIM, DDIM);

        splitw(w1[p], FFD * DDIM);   gemm_f(prh, prl, h1, BSR, FFD, DDIM);
        splitw(w3[p], FFD * DDIM);   gemm_f(prh, prl, h3, BSR, FFD, DDIM);

        silu_mul_split_kernel<<<(n4ff + 255) / 256, 256>>>(h1, h3, hsh, hsl, n4ff);

        splitw(w2[p], DDIM * FFD);   gemm_f(hsh, hsl, ff, BSR, DDIM, FFD);

        rms_resid_out_kernel<<<BSR, 256>>>(ff, resid, fnw[p],
                                           out + (size_t)p * BSR * DDIM);
    }
}

// round 9
// speedup vs baseline: 1.4979x; 1.4979x over previous
#include <cuda_runtime.h>
#include <cuda_bf16.h>
#include <math.h>
#include <stdint.h>

// Problem constants
#define BB   2
#define SS   2048
#define DDIM 2048
#define HH   16
#define HDIM 128
#define FFD  5632
#define BSR  (BB * SS)          // 4096 rows total
#define EPSV 1e-5f

// ---------------------------------------------------------------------------
// Scratch (static device globals — no allocations allowed)
// ---------------------------------------------------------------------------
__device__ float g_h1[BSR * FFD];
__device__ float g_h3[BSR * FFD];
__device__ float g_ff[BSR * DDIM];

__device__ __nv_bfloat16 g_xn_h[BSR * DDIM], g_xn_l[BSR * DDIM];
__device__ __nv_bfloat16 g_yn_h[BSR * DDIM], g_yn_l[BSR * DDIM];
__device__ __nv_bfloat16 g_q_h [BSR * DDIM], g_q_l [BSR * DDIM];
__device__ __nv_bfloat16 g_k_h [BSR * DDIM], g_k_l [BSR * DDIM];
__device__ __nv_bfloat16 g_v_h [BSR * DDIM], g_v_l [BSR * DDIM];
__device__ __nv_bfloat16 g_att_h[BSR * DDIM], g_att_l[BSR * DDIM];
__device__ __nv_bfloat16 g_pr_h[BSR * DDIM], g_pr_l[BSR * DDIM];
__device__ __nv_bfloat16 g_hs_h[BSR * FFD],  g_hs_l[BSR * FFD];
__device__ __nv_bfloat16 g_w_h [FFD * DDIM], g_w_l [FFD * DDIM];

// ---------------------------------------------------------------------------
// Helpers (baseline PTX only — build targets compute_103)
// ---------------------------------------------------------------------------
__device__ __forceinline__ void mma_bf16(float* d, const uint32_t* a, const uint32_t* b) {
    asm volatile(
        "mma.sync.aligned.m16n8k16.row.col.f32.bf16.bf16.f32 "
        "{%0,%1,%2,%3}, {%4,%5,%6,%7}, {%8,%9}, {%0,%1,%2,%3};"
        : "+f"(d[0]), "+f"(d[1]), "+f"(d[2]), "+f"(d[3])
        : "r"(a[0]), "r"(a[1]), "r"(a[2]), "r"(a[3]), "r"(b[0]), "r"(b[1]));
}
__device__ __forceinline__ void ldsm_x4(uint32_t* r, uint32_t a) {
    asm volatile("ldmatrix.sync.aligned.m8n8.x4.shared.b16 {%0,%1,%2,%3}, [%4];"
                 : "=r"(r[0]), "=r"(r[1]), "=r"(r[2]), "=r"(r[3]) : "r"(a));
}
__device__ __forceinline__ void ldsm_x2(uint32_t* r, uint32_t a) {
    asm volatile("ldmatrix.sync.aligned.m8n8.x2.shared.b16 {%0,%1}, [%2];"
                 : "=r"(r[0]), "=r"(r[1]) : "r"(a));
}
__device__ __forceinline__ void ldsm_x2t(uint32_t* r, uint32_t a) {
    asm volatile("ldmatrix.sync.aligned.m8n8.x2.trans.shared.b16 {%0,%1}, [%2];"
                 : "=r"(r[0]), "=r"(r[1]) : "r"(a));
}
__device__ __forceinline__ uint32_t smem_u32(const void* p) {
    uint32_t a;
    asm("{ .reg .u64 t; cvta.to.shared.u64 t, %1; cvt.u32.u64 %0, t; }" : "=r"(a) : "l"(p));
    return a;
}
// pack two fp32 -> bf16x2 (lo = first element)
__device__ __forceinline__ uint32_t cvt_bf16x2(float hi, float lo) {
    uint32_t r;
    asm("cvt.rn.bf16x2.f32 %0, %1, %2;" : "=r"(r) : "f"(hi), "f"(lo));
    return r;
}
__device__ __forceinline__ float un_lo(uint32_t u) { return __uint_as_float(u << 16); }
__device__ __forceinline__ float un_hi(uint32_t u) { return __uint_as_float(u & 0xffff0000u); }

// ---------------------------------------------------------------------------
// fp32 -> bf16 hi/lo split (weights)
// ---------------------------------------------------------------------------
__global__ __launch_bounds__(256) void split_bf16_kernel(
    const float* __restrict__ in, __nv_bfloat16* __restrict__ hi,
    __nv_bfloat16* __restrict__ lo, int n4)
{
    const int i = blockIdx.x * 256 + threadIdx.x;
    if (i >= n4) return;
    float4 v = ((const float4*)in)[i];
    uint32_t h0 = cvt_bf16x2(v.y, v.x);
    uint32_t h1 = cvt_bf16x2(v.w, v.z);
    uint32_t l0 = cvt_bf16x2(v.y - un_hi(h0), v.x - un_lo(h0));
    uint32_t l1 = cvt_bf16x2(v.w - un_hi(h1), v.z - un_lo(h1));
    ((uint2*)hi)[i] = make_uint2(h0, h1);
    ((uint2*)lo)[i] = make_uint2(l0, l1);
}

// ---------------------------------------------------------------------------
// bf16x3 GEMM (mma.sync + ldmatrix): C[M,N] = A[M,K] @ B[N,K]^T, fp32 accum.
// C += Ah*Bh + Ah*Bl + Al*Bh.  Tile 128x128, Kc=64 (128B rows, XOR swizzle),
// 256 threads / 8 warps (4m x 2n, warp tile 32x64), double-buffered SMEM with
// register prefetch of the next chunk overlapping compute.
// ---------------------------------------------------------------------------
#define GEMM_TILE_BYTES 16384
#define GEMM_BUF_BYTES  (4 * GEMM_TILE_BYTES)
#define GEMM_SMEM       (2 * GEMM_BUF_BYTES + 1024)

__global__ __launch_bounds__(256, 1)
void gemm_bf16x3(const __nv_bfloat16* __restrict__ Ah, const __nv_bfloat16* __restrict__ Al,
                 const __nv_bfloat16* __restrict__ Bh, const __nv_bfloat16* __restrict__ Bl,
                 float* __restrict__ C,
                 __nv_bfloat16* __restrict__ Ch, __nv_bfloat16* __restrict__ Cl,
                 int M, int N, int K)
{
    extern __shared__ char dyn[];
    const int tid  = threadIdx.x;
    const int wid  = tid >> 5;
    const int lane = tid & 31;
    const int wm   = wid >> 1;        // 0..3
    const int wn   = wid & 1;         // 0..1
    const int bm   = blockIdx.y * 128;
    const int bn   = blockIdx.x * 128;

    const uint32_t dyn_u  = smem_u32(dyn);
    const uint32_t tile_u = (dyn_u + 1023u) & ~1023u;
    char* tile_p = dyn + (tile_u - dyn_u);

    const int nk   = K >> 6;
    const int grow = tid >> 1;                 // 0..127
    const __nv_bfloat16* pAh = Ah + (size_t)(bm + grow) * K + (tid & 1) * 32;
    const __nv_bfloat16* pAl = Al + (size_t)(bm + grow) * K + (tid & 1) * 32;
    const __nv_bfloat16* pBh = Bh + (size_t)(bn + grow) * K + (tid & 1) * 32;
    const __nv_bfloat16* pBl = Bl + (size_t)(bn + grow) * K + (tid & 1) * 32;

    uint32_t soff[4];
#pragma unroll
    for (int j = 0; j < 4; j++) {
        uint32_t off = (uint32_t)(grow * 128 + (tid & 1) * 64 + j * 16);
        soff[j] = off ^ ((off >> 3) & 0x70u);
    }

    // ldmatrix per-lane addressing constants
    const int lr8   = lane & 7;
    const int rAo   = wm * 32 + lr8 + ((lane >> 3) & 1) * 8;  // + mi*16
    const int kaddA = ((lane >> 4) & 1) * 16;
    const int kaddB = ((lane >> 3) & 1) * 16;
    const uint32_t rBbase = (uint32_t)((wn * 64 + lr8) * 128);

    float acc[2][8][4];
#pragma unroll
    for (int mi = 0; mi < 2; mi++)
#pragma unroll
        for (int j = 0; j < 8; j++)
#pragma unroll
            for (int q = 0; q < 4; q++) acc[mi][j][q] = 0.f;

    uint4 pref[16];

    auto ldreg = [&](int i) {
        const uint4* a_h = (const uint4*)(pAh + (i << 6));
        const uint4* a_l = (const uint4*)(pAl + (i << 6));
        const uint4* b_h = (const uint4*)(pBh + (i << 6));
        const uint4* b_l = (const uint4*)(pBl + (i << 6));
#pragma unroll
        for (int j = 0; j < 4; j++) {
            pref[j]      = a_h[j];
            pref[4 + j]  = a_l[j];
            pref[8 + j]  = b_h[j];
            pref[12 + j] = b_l[j];
        }
    };
    auto stbuf = [&](int b) {
        char* base = tile_p + b * GEMM_BUF_BYTES;
#pragma unroll
        for (int j = 0; j < 4; j++) {
            *(uint4*)(base + soff[j])                       = pref[j];
            *(uint4*)(base + GEMM_TILE_BYTES + soff[j])     = pref[4 + j];
            *(uint4*)(base + 2 * GEMM_TILE_BYTES + soff[j]) = pref[8 + j];
            *(uint4*)(base + 3 * GEMM_TILE_BYTES + soff[j]) = pref[12 + j];
        }
    };

    ldreg(0);
    stbuf(0);
    __syncthreads();

    for (int i = 0; i < nk; i++) {
        if (i + 1 < nk) ldreg(i + 1);

        const uint32_t bu = tile_u + (uint32_t)(i & 1) * GEMM_BUF_BYTES;
#pragma unroll
        for (int ks = 0; ks < 4; ks++) {
            const int kb = ks * 32;
            const uint32_t swA = (uint32_t)(kb + kaddA) ^ ((uint32_t)lr8 << 4);
            const uint32_t swB = (uint32_t)(kb + kaddB) ^ ((uint32_t)lr8 << 4);
            uint32_t ah[2][4], al2[2][4];
#pragma unroll
            for (int mi = 0; mi < 2; mi++) {
                const uint32_t ra = (uint32_t)((rAo + mi * 16) * 128);
                ldsm_x4(ah[mi],  bu + ra + swA);
                ldsm_x4(al2[mi], bu + GEMM_TILE_BYTES + ra + swA);
            }
#pragma unroll
            for (int j = 0; j < 8; j++) {
                const uint32_t rb = rBbase + (uint32_t)(j * 8 * 128);
                uint32_t bh[2], bl[2];
                ldsm_x2(bh, bu + 2 * GEMM_TILE_BYTES + rb + swB);
                ldsm_x2(bl, bu + 3 * GEMM_TILE_BYTES + rb + swB);
                mma_bf16(acc[0][j], ah[0], bh);
                mma_bf16(acc[1][j], ah[1], bh);
                mma_bf16(acc[0][j], ah[0], bl);
                mma_bf16(acc[1][j], ah[1], bl);
                mma_bf16(acc[0][j], al2[0], bh);
                mma_bf16(acc[1][j], al2[1], bh);
            }
        }
        __syncthreads();
        if (i + 1 < nk) {
            stbuf((i + 1) & 1);
            __syncthreads();
        }
    }

    const int lr = lane >> 2;
    if (Ch) {
#pragma unroll
        for (int mi = 0; mi < 2; mi++) {
            const int r0 = bm + wm * 32 + mi * 16 + lr;
#pragma unroll
            for (int j = 0; j < 8; j++) {
                const int col = bn + wn * 64 + j * 8 + ((lane & 3) << 1);
                uint32_t h0 = cvt_bf16x2(acc[mi][j][1], acc[mi][j][0]);
                uint32_t l0 = cvt_bf16x2(acc[mi][j][1] - un_hi(h0), acc[mi][j][0] - un_lo(h0));
                uint32_t h1 = cvt_bf16x2(acc[mi][j][3], acc[mi][j][2]);
                uint32_t l1 = cvt_bf16x2(acc[mi][j][3] - un_hi(h1), acc[mi][j][2] - un_lo(h1));
                *(uint32_t*)(Ch + (size_t)r0 * N + col)       = h0;
                *(uint32_t*)(Cl + (size_t)r0 * N + col)       = l0;
                *(uint32_t*)(Ch + (size_t)(r0 + 8) * N + col) = h1;
                *(uint32_t*)(Cl + (size_t)(r0 + 8) * N + col) = l1;
            }
        }
    } else {
#pragma unroll
        for (int mi = 0; mi < 2; mi++) {
            const int r0 = bm + wm * 32 + mi * 16 + lr;
#pragma unroll
            for (int j = 0; j < 8; j++) {
                const int col = bn + wn * 64 + j * 8 + ((lane & 3) << 1);
                *(float2*)(C + (size_t)r0 * N + col)       = make_float2(acc[mi][j][0], acc[mi][j][1]);
                *(float2*)(C + (size_t)(r0 + 8) * N + col) = make_float2(acc[mi][j][2], acc[mi][j][3]);
            }
        }
    }
}

// ---------------------------------------------------------------------------
// Flash attention, tensor-core bf16x3 (mma.sync + ldmatrix).
// 256 threads / 8 warps; q-tile 128 (warp w owns q rows w*16..w*16+15).
// Q/K kv-major tiles [rows][256B] XOR-swizzled; V kv-major too, B-fragments
// produced by ldmatrix.x2.trans (no explicit transpose).
// SMEM: Qh,Ql [128][256] + Kh,Kl,Vh,Vl [64][256] = 128KB dynamic.
// ---------------------------------------------------------------------------
#define FL_SMEM (2 * 32768 + 4 * 16384)

__global__ __launch_bounds__(256, 1) void flash_bf16_kernel(
    const __nv_bfloat16* __restrict__ Qh_g, const __nv_bfloat16* __restrict__ Ql_g,
    const __nv_bfloat16* __restrict__ Kh_g, const __nv_bfloat16* __restrict__ Kl_g,
    const __nv_bfloat16* __restrict__ Vh_g, const __nv_bfloat16* __restrict__ Vl_g,
    __nv_bfloat16* __restrict__ Oh_g, __nv_bfloat16* __restrict__ Ol_g)
{
    extern __shared__ char sm[];
    char* sQh = sm;
    char* sQl = sm + 32768;
    char* sKh = sm + 65536;
    char* sKl = sm + 65536 + 16384;
    char* sVh = sm + 65536 + 2 * 16384;
    char* sVl = sm + 65536 + 3 * 16384;
    const uint32_t sm_u = smem_u32(sm);
    const uint32_t uQh = sm_u, uQl = sm_u + 32768;
    const uint32_t uKh = sm_u + 65536, uKl = uKh + 16384;
    const uint32_t uVh = uKl + 16384,  uVl = uVh + 16384;

    const int tid  = threadIdx.x;
    const int wid  = tid >> 5;        // 0..7
    const int lane = tid & 31;
    const int lr   = lane >> 2;
    const int c0   = lane & 3;
    const int q0   = blockIdx.x * 128;
    const int h    = blockIdx.y;
    const int b    = blockIdx.z;
    const size_t rowbase = (size_t)b * SS;
    const float scale = 0.0883883476483184405f;   // 1/sqrt(128)

    // ldmatrix addressing constants
    const int lr8   = lane & 7;
    const int rQ    = wid * 16 + lr8 + ((lane >> 3) & 1) * 8;
    const int kaddA = ((lane >> 4) & 1) * 16;
    const int kaddB = ((lane >> 3) & 1) * 16;
    const int kvro  = lr8 + ((lane >> 3) & 1) * 8;   // + kvks*16 (V trans rows)

    // ---- load Q tile (hi/lo): 128 rows x 256B, swizzled ----
    {
        const char* qh = (const char*)(Qh_g + (rowbase + q0) * DDIM + h * HDIM);
        const char* ql = (const char*)(Ql_g + (rowbase + q0) * DDIM + h * HDIM);
#pragma unroll
        for (int it = 0; it < 8; it++) {
            int li = tid + it * 256;
            int r = li >> 4, c = (li & 15) * 16;
            uint32_t sw = (uint32_t)c ^ (((uint32_t)r & 7u) << 4);
            *(uint4*)(sQh + r * 256 + sw) = *(const uint4*)(qh + (size_t)r * (DDIM * 2) + c);
            *(uint4*)(sQl + r * 256 + sw) = *(const uint4*)(ql + (size_t)r * (DDIM * 2) + c);
        }
    }

    float o[16][4];
#pragma unroll
    for (int j = 0; j < 16; j++)
#pragma unroll
        for (int q = 0; q < 4; q++) o[j][q] = 0.f;
    float m0 = -1e30f, m1 = -1e30f, l0 = 0.f, l1 = 0.f;

    for (int t = 0; t < SS / 64; t++) {
        __syncthreads();
        {
            const char* kh = (const char*)(Kh_g + (rowbase + t * 64) * DDIM + h * HDIM);
            const char* kl = (const char*)(Kl_g + (rowbase + t * 64) * DDIM + h * HDIM);
            const char* vh = (const char*)(Vh_g + (rowbase + t * 64) * DDIM + h * HDIM);
            const char* vl = (const char*)(Vl_g + (rowbase + t * 64) * DDIM + h * HDIM);
#pragma unroll
            for (int it = 0; it < 4; it++) {
                int li = tid + it * 256;
                int r = li >> 4, c = (li & 15) * 16;
                uint32_t sw = (uint32_t)c ^ (((uint32_t)r & 7u) << 4);
                *(uint4*)(sKh + r * 256 + sw) = *(const uint4*)(kh + (size_t)r * (DDIM * 2) + c);
                *(uint4*)(sKl + r * 256 + sw) = *(const uint4*)(kl + (size_t)r * (DDIM * 2) + c);
                *(uint4*)(sVh + r * 256 + sw) = *(const uint4*)(vh + (size_t)r * (DDIM * 2) + c);
                *(uint4*)(sVl + r * 256 + sw) = *(const uint4*)(vl + (size_t)r * (DDIM * 2) + c);
            }
        }
        __syncthreads();

        // ---- S = Q K^T (bf16x3): warp rows {wid*16+lr, +8}, 64 kv cols ----
        float s[8][4];
#pragma unroll
        for (int j = 0; j < 8; j++)
#pragma unroll
            for (int q = 0; q < 4; q++) s[j][q] = 0.f;

#pragma unroll
        for (int ks = 0; ks < 8; ks++) {
            const int kb = ks * 32;
            const uint32_t swA = (uint32_t)(kb + kaddA) ^ ((uint32_t)lr8 << 4);
            const uint32_t swB = (uint32_t)(kb + kaddB) ^ ((uint32_t)lr8 << 4);
            uint32_t qh4[4], ql4[4];
            ldsm_x4(qh4, uQh + (uint32_t)(rQ * 256) + swA);
            ldsm_x4(ql4, uQl + (uint32_t)(rQ * 256) + swA);
#pragma unroll
            for (int j = 0; j < 8; j++) {
                const uint32_t rb = (uint32_t)((j * 8 + lr8) * 256);
                uint32_t kh2[2], kl2[2];
                ldsm_x2(kh2, uKh + rb + swB);
                ldsm_x2(kl2, uKl + rb + swB);
                mma_bf16(s[j], qh4, kh2);
                mma_bf16(s[j], qh4, kl2);
                mma_bf16(s[j], ql4, kh2);
            }
        }

        // ---- online softmax (rows wid*16+lr and +8) ----
        float mx0 = -1e30f, mx1 = -1e30f;
#pragma unroll
        for (int j = 0; j < 8; j++) {
            s[j][0] *= scale; s[j][1] *= scale; s[j][2] *= scale; s[j][3] *= scale;
            mx0 = fmaxf(mx0, fmaxf(s[j][0], s[j][1]));
            mx1 = fmaxf(mx1, fmaxf(s[j][2], s[j][3]));
        }
        mx0 = fmaxf(mx0, __shfl_xor_sync(0xffffffffu, mx0, 1));
        mx0 = fmaxf(mx0, __shfl_xor_sync(0xffffffffu, mx0, 2));
        mx1 = fmaxf(mx1, __shfl_xor_sync(0xffffffffu, mx1, 1));
        mx1 = fmaxf(mx1, __shfl_xor_sync(0xffffffffu, mx1, 2));
        const float mn0 = fmaxf(m0, mx0), mn1 = fmaxf(m1, mx1);
        const float al0 = __expf(m0 - mn0), al1 = __expf(m1 - mn1);

        uint32_t pah[4][4], pal[4][4];
        float rs0 = 0.f, rs1 = 0.f;
#pragma unroll
        for (int j = 0; j < 8; j++) {
            float p0 = __expf(s[j][0] - mn0);
            float p1 = __expf(s[j][1] - mn0);
            float p2 = __expf(s[j][2] - mn1);
            float p3 = __expf(s[j][3] - mn1);
            rs0 += p0 + p1; rs1 += p2 + p3;
            uint32_t h01 = cvt_bf16x2(p1, p0);
            uint32_t h23 = cvt_bf16x2(p3, p2);
            uint32_t q01 = cvt_bf16x2(p1 - un_hi(h01), p0 - un_lo(h01));
            uint32_t q23 = cvt_bf16x2(p3 - un_hi(h23), p2 - un_lo(h23));
            const int kvks = j >> 1, half = (j & 1) << 1;
            pah[kvks][half]     = h01;
            pah[kvks][half + 1] = h23;
            pal[kvks][half]     = q01;
            pal[kvks][half + 1] = q23;
        }
        rs0 += __shfl_xor_sync(0xffffffffu, rs0, 1);
        rs0 += __shfl_xor_sync(0xffffffffu, rs0, 2);
        rs1 += __shfl_xor_sync(0xffffffffu, rs1, 1);
        rs1 += __shfl_xor_sync(0xffffffffu, rs1, 2);
        l0 = l0 * al0 + rs0;
        l1 = l1 * al1 + rs1;
        m0 = mn0; m1 = mn1;
#pragma unroll
        for (int jn = 0; jn < 16; jn++) {
            o[jn][0] *= al0; o[jn][1] *= al0;
            o[jn][2] *= al1; o[jn][3] *= al1;
        }

        // ---- O += P V (bf16x3); V fragments via ldmatrix.trans ----
#pragma unroll
        for (int kvks = 0; kvks < 4; kvks++) {
            const uint32_t* pa = pah[kvks];
            const uint32_t* pl = pal[kvks];
            const uint32_t kvr = (uint32_t)((kvks * 16 + kvro) * 256);
            const uint32_t swr = ((uint32_t)lr8 << 4);
#pragma unroll
            for (int jn = 0; jn < 16; jn++) {
                const uint32_t swV = ((uint32_t)(jn * 16)) ^ swr;
                uint32_t vh2[2], vl2[2];
                ldsm_x2t(vh2, uVh + kvr + swV);
                ldsm_x2t(vl2, uVl + kvr + swV);
                mma_bf16(o[jn], pa, vh2);
                mma_bf16(o[jn], pa, vl2);
                mma_bf16(o[jn], pl, vh2);
            }
        }
    }

    // ---- normalize and store att as bf16 hi/lo ----
    const float i0 = 1.f / l0, i1 = 1.f / l1;
    const size_t rg0 = rowbase + q0 + wid * 16 + lr;
    const int colb = h * HDIM + (c0 << 1);
#pragma unroll
    for (int jn = 0; jn < 16; jn++) {
        float v0 = o[jn][0] * i0, v1 = o[jn][1] * i0;
        float v2 = o[jn][2] * i1, v3 = o[jn][3] * i1;
        uint32_t h01 = cvt_bf16x2(v1, v0);
        uint32_t l01 = cvt_bf16x2(v1 - un_hi(h01), v0 - un_lo(h01));
        uint32_t h23 = cvt_bf16x2(v3, v2);
        uint32_t l23 = cvt_bf16x2(v3 - un_hi(h23), v2 - un_lo(h23));
        const size_t off0 = rg0 * DDIM + colb + jn * 8;
        const size_t off1 = (rg0 + 8) * DDIM + colb + jn * 8;
        *(uint32_t*)(Oh_g + off0) = h01;
        *(uint32_t*)(Ol_g + off0) = l01;
        *(uint32_t*)(Oh_g + off1) = h23;
        *(uint32_t*)(Ol_g + off1) = l23;
    }
}

// ---------------------------------------------------------------------------
// RMSNorm with fused bf16 hi/lo split output
// ---------------------------------------------------------------------------
__global__ __launch_bounds__(256) void rmsnorm_split_kernel(
    const float* __restrict__ in, const float* __restrict__ w,
    __nv_bfloat16* __restrict__ oh, __nv_bfloat16* __restrict__ ol)
{
    const int row  = blockIdx.x;
    const int base = threadIdx.x * 8;
    const float* r = in + (size_t)row * DDIM;

    float v[8];
    *(float4*)(v)     = *(const float4*)(r + base);
    *(float4*)(v + 4) = *(const float4*)(r + base + 4);

    float ss = 0.f;
#pragma unroll
    for (int i = 0; i < 8; i++) ss += v[i] * v[i];
#pragma unroll
    for (int o = 16; o > 0; o >>= 1) ss += __shfl_xor_sync(0xffffffffu, ss, o);

    __shared__ float red[8];
    __shared__ float sscale;
    if ((threadIdx.x & 31) == 0) red[threadIdx.x >> 5] = ss;
    __syncthreads();
    if (threadIdx.x == 0) {
        float t = 0.f;
#pragma unroll
        for (int i = 0; i < 8; i++) t += red[i];
        sscale = rsqrtf(t / (float)DDIM + EPSV);
    }
    __syncthreads();
    const float sc = sscale;

    uint32_t hh[4], ll[4];
#pragma unroll
    for (int p = 0; p < 4; p++) {
        float f0 = v[2 * p]     * sc * w[base + 2 * p];
        float f1 = v[2 * p + 1] * sc * w[base + 2 * p + 1];
        hh[p] = cvt_bf16x2(f1, f0);
        ll[p] = cvt_bf16x2(f1 - un_hi(hh[p]), f0 - un_lo(hh[p]));
    }
    *(uint4*)(oh + (size_t)row * DDIM + base) = make_uint4(hh[0], hh[1], hh[2], hh[3]);
    *(uint4*)(ol + (size_t)row * DDIM + base) = make_uint4(ll[0], ll[1], ll[2], ll[3]);
}

// ---------------------------------------------------------------------------
// RMSNorm of (ff + residual) -> final fp32 output
// ---------------------------------------------------------------------------
__global__ __launch_bounds__(256) void rms_resid_out_kernel(
    const float* __restrict__ ff, const float* __restrict__ res,
    const float* __restrict__ w, float* __restrict__ out)
{
    const int row  = blockIdx.x;
    const int base = threadIdx.x * 8;
    const float* f = ff  + (size_t)row * DDIM;
    const float* r = res + (size_t)row * DDIM;

    float4 a0 = *(const float4*)(f + base);
    float4 a1 = *(const float4*)(f + base + 4);
    float4 b0 = *(const float4*)(r + base);
    float4 b1 = *(const float4*)(r + base + 4);

    float v[8];
    v[0] = a0.x + b0.x; v[1] = a0.y + b0.y; v[2] = a0.z + b0.z; v[3] = a0.w + b0.w;
    v[4] = a1.x + b1.x; v[5] = a1.y + b1.y; v[6] = a1.z + b1.z; v[7] = a1.w + b1.w;

    float ss = 0.f;
#pragma unroll
    for (int i = 0; i < 8; i++) ss += v[i] * v[i];
#pragma unroll
    for (int o = 16; o > 0; o >>= 1) ss += __shfl_xor_sync(0xffffffffu, ss, o);

    __shared__ float red[8];
    __shared__ float sscale;
    if ((threadIdx.x & 31) == 0) red[threadIdx.x >> 5] = ss;
    __syncthreads();
    if (threadIdx.x == 0) {
        float t = 0.f;
#pragma unroll
        for (int i = 0; i < 8; i++) t += red[i];
        sscale = rsqrtf(t / (float)DDIM + EPSV);
    }
    __syncthreads();
    const float sc = sscale;

    float o8[8];
#pragma unroll
    for (int i = 0; i < 8; i++) o8[i] = v[i] * sc * w[base + i];
    float* op = out + (size_t)row * DDIM + base;
    *(float4*)(op)     = *(float4*)(o8);
    *(float4*)(op + 4) = *(float4*)(o8 + 4);
}

// ---------------------------------------------------------------------------
// SiLU-mul with fused bf16 hi/lo split output: hs = silu(h1) * h3
// ---------------------------------------------------------------------------
__global__ __launch_bounds__(256) void silu_mul_split_kernel(
    const float* __restrict__ h1, const float* __restrict__ h3,
    __nv_bfloat16* __restrict__ oh, __nv_bfloat16* __restrict__ ol, int n4)
{
    const int i = blockIdx.x * 256 + threadIdx.x;
    if (i >= n4) return;
    float4 a = ((const float4*)h1)[i];
    float4 b = ((const float4*)h3)[i];
    float r0 = a.x * (1.f / (1.f + __expf(-a.x))) * b.x;
    float r1 = a.y * (1.f / (1.f + __expf(-a.y))) * b.y;
    float r2 = a.z * (1.f / (1.f + __expf(-a.z))) * b.z;
    float r3 = a.w * (1.f / (1.f + __expf(-a.w))) * b.w;
    uint32_t h0 = cvt_bf16x2(r1, r0);
    uint32_t h1u = cvt_bf16x2(r3, r2);
    uint32_t l0 = cvt_bf16x2(r1 - un_hi(h0), r0 - un_lo(h0));
    uint32_t l1 = cvt_bf16x2(r3 - un_hi(h1u), r2 - un_lo(h1u));
    ((uint2*)oh)[i] = make_uint2(h0, h1u);
    ((uint2*)ol)[i] = make_uint2(l0, l1);
}

// ---------------------------------------------------------------------------
// Host orchestration
// ---------------------------------------------------------------------------
extern "C" void kernel_launch(void* const* d_in, const int* in_sizes, int n_in,
                              void* d_out, int out_size)
{
    (void)in_sizes; (void)n_in; (void)out_size;

    const float* x           = (const float*)d_in[0];
    const float* y           = (const float*)d_in[1];
    const float* attn_norm_w = (const float*)d_in[2];
    const float* wq[2]  = {(const float*)d_in[3],  (const float*)d_in[7]};
    const float* wk[2]  = {(const float*)d_in[4],  (const float*)d_in[8]};
    const float* wv[2]  = {(const float*)d_in[5],  (const float*)d_in[9]};
    const float* wo[2]  = {(const float*)d_in[6],  (const float*)d_in[10]};
    const float* w1[2]  = {(const float*)d_in[11], (const float*)d_in[15]};
    const float* w2[2]  = {(const float*)d_in[12], (const float*)d_in[16]};
    const float* w3[2]  = {(const float*)d_in[13], (const float*)d_in[17]};
    const float* fnw[2] = {(const float*)d_in[14], (const float*)d_in[18]};
    float* out = (float*)d_out;

    float *h1, *h3, *ff;
    cudaGetSymbolAddress((void**)&h1, g_h1);
    cudaGetSymbolAddress((void**)&h3, g_h3);
    cudaGetSymbolAddress((void**)&ff, g_ff);

    __nv_bfloat16 *xnh, *xnl, *ynh, *ynl, *qh, *ql, *kh, *kl, *vh, *vl;
    __nv_bfloat16 *ath, *atl, *prh, *prl, *hsh, *hsl, *wh, *wl;
    cudaGetSymbolAddress((void**)&xnh, g_xn_h); cudaGetSymbolAddress((void**)&xnl, g_xn_l);
    cudaGetSymbolAddress((void**)&ynh, g_yn_h); cudaGetSymbolAddress((void**)&ynl, g_yn_l);
    cudaGetSymbolAddress((void**)&qh,  g_q_h);  cudaGetSymbolAddress((void**)&ql,  g_q_l);
    cudaGetSymbolAddress((void**)&kh,  g_k_h);  cudaGetSymbolAddress((void**)&kl,  g_k_l);
    cudaGetSymbolAddress((void**)&vh,  g_v_h);  cudaGetSymbolAddress((void**)&vl,  g_v_l);
    cudaGetSymbolAddress((void**)&ath, g_att_h); cudaGetSymbolAddress((void**)&atl, g_att_l);
    cudaGetSymbolAddress((void**)&prh, g_pr_h); cudaGetSymbolAddress((void**)&prl, g_pr_l);
    cudaGetSymbolAddress((void**)&hsh, g_hs_h); cudaGetSymbolAddress((void**)&hsl, g_hs_l);
    cudaGetSymbolAddress((void**)&wh,  g_w_h);  cudaGetSymbolAddress((void**)&wl,  g_w_l);

    cudaFuncSetAttribute(gemm_bf16x3,
                         cudaFuncAttributeMaxDynamicSharedMemorySize, GEMM_SMEM);
    cudaFuncSetAttribute(flash_bf16_kernel,
                         cudaFuncAttributeMaxDynamicSharedMemorySize, FL_SMEM);

    // Pre-norms with fused hi/lo split
    rmsnorm_split_kernel<<<BSR, 256>>>(x, attn_norm_w, xnh, xnl);
    rmsnorm_split_kernel<<<BSR, 256>>>(y, attn_norm_w, ynh, ynl);

    const dim3 gAttn(SS / 128, HH, BB);
    const int  n4ff = BSR * FFD / 4;

    auto splitw = [&](const float* src, int n) {
        int n4s = n / 4;
        split_bf16_kernel<<<(n4s + 255) / 256, 256>>>(src, wh, wl, n4s);
    };
    auto gemm_s = [&](const __nv_bfloat16* Ah_, const __nv_bfloat16* Al_,
                      __nv_bfloat16* Ch_, __nv_bfloat16* Cl_, int M, int N, int K) {
        dim3 g(N / 128, M / 128);
        gemm_bf16x3<<<g, 256, GEMM_SMEM>>>(Ah_, Al_, wh, wl, nullptr, Ch_, Cl_, M, N, K);
    };
    auto gemm_f = [&](const __nv_bfloat16* Ah_, const __nv_bfloat16* Al_,
                      float* C_, int M, int N, int K) {
        dim3 g(N / 128, M / 128);
        gemm_bf16x3<<<g, 256, GEMM_SMEM>>>(Ah_, Al_, wh, wl, C_, nullptr, nullptr, M, N, K);
    };

    for (int p = 0; p < 2; p++) {
        const __nv_bfloat16* qih = (p == 0) ? xnh : ynh;
        const __nv_bfloat16* qil = (p == 0) ? xnl : ynl;
        const __nv_bfloat16* kih = (p == 0) ? ynh : xnh;
        const __nv_bfloat16* kil = (p == 0) ? ynl : xnl;
        const float* resid = (p == 0) ? x : y;

        splitw(wq[p], DDIM * DDIM);  gemm_s(qih, qil, qh, ql, BSR, DDIM, DDIM);
        splitw(wk[p], DDIM * DDIM);  gemm_s(kih, kil, kh, kl, BSR, DDIM, DDIM);
        splitw(wv[p], DDIM * DDIM);  gemm_s(kih, kil, vh, vl, BSR, DDIM, DDIM);

        flash_bf16_kernel<<<gAttn, 256, FL_SMEM>>>(qh, ql, kh, kl, vh, vl, ath, atl);

        splitw(wo[p], DDIM * DDIM);  gemm_s(ath, atl, prh, prl, BSR, DDIM, DDIM);

        splitw(w1[p], FFD * DDIM);   gemm_f(prh, prl, h1, BSR, FFD, DDIM);
        splitw(w3[p], FFD * DDIM);   gemm_f(prh, prl, h3, BSR, FFD, DDIM);

        silu_mul_split_kernel<<<(n4ff + 255) / 256, 256>>>(h1, h3, hsh, hsl, n4ff);

        splitw(w2[p], DDIM * FFD);   gemm_f(hsh, hsl, ff, BSR, DDIM, FFD);

        rms_resid_out_kernel<<<BSR, 256>>>(ff, resid, fnw[p],
                                           out + (size_t)p * BSR * DDIM);
    }
}

// round 11
// speedup vs baseline: 1.5816x; 1.0559x over previous
#include <cuda_runtime.h>
#include <cuda_bf16.h>
#include <math.h>
#include <stdint.h>

// Problem constants
#define BB   2
#define SS   2048
#define DDIM 2048
#define HH   16
#define HDIM 128
#define FFD  5632
#define BSR  (BB * SS)          // 4096 rows total
#define EPSV 1e-5f

// ---------------------------------------------------------------------------
// Scratch (static device globals — no allocations allowed)
// ---------------------------------------------------------------------------
__device__ float g_h1[BSR * FFD];
__device__ float g_h3[BSR * FFD];
__device__ float g_ff[BSR * DDIM];

__device__ __nv_bfloat16 g_xn_h[BSR * DDIM], g_xn_l[BSR * DDIM];
__device__ __nv_bfloat16 g_yn_h[BSR * DDIM], g_yn_l[BSR * DDIM];
__device__ __nv_bfloat16 g_q_h [BSR * DDIM], g_q_l [BSR * DDIM];
__device__ __nv_bfloat16 g_k_h [BSR * DDIM], g_k_l [BSR * DDIM];
__device__ __nv_bfloat16 g_v_h [BSR * DDIM], g_v_l [BSR * DDIM];
__device__ __nv_bfloat16 g_att_h[BSR * DDIM], g_att_l[BSR * DDIM];
__device__ __nv_bfloat16 g_pr_h[BSR * DDIM], g_pr_l[BSR * DDIM];
__device__ __nv_bfloat16 g_hs_h[BSR * FFD],  g_hs_l[BSR * FFD];
__device__ __nv_bfloat16 g_w_h [FFD * DDIM], g_w_l [FFD * DDIM];

// ---------------------------------------------------------------------------
// Helpers (baseline PTX only — build targets compute_103)
// ---------------------------------------------------------------------------
__device__ __forceinline__ void mma_bf16(float* d, const uint32_t* a, const uint32_t* b) {
    asm volatile(
        "mma.sync.aligned.m16n8k16.row.col.f32.bf16.bf16.f32 "
        "{%0,%1,%2,%3}, {%4,%5,%6,%7}, {%8,%9}, {%0,%1,%2,%3};"
        : "+f"(d[0]), "+f"(d[1]), "+f"(d[2]), "+f"(d[3])
        : "r"(a[0]), "r"(a[1]), "r"(a[2]), "r"(a[3]), "r"(b[0]), "r"(b[1]));
}
__device__ __forceinline__ void ldsm_x4(uint32_t* r, uint32_t a) {
    asm volatile("ldmatrix.sync.aligned.m8n8.x4.shared.b16 {%0,%1,%2,%3}, [%4];"
                 : "=r"(r[0]), "=r"(r[1]), "=r"(r[2]), "=r"(r[3]) : "r"(a));
}
__device__ __forceinline__ void ldsm_x2(uint32_t* r, uint32_t a) {
    asm volatile("ldmatrix.sync.aligned.m8n8.x2.shared.b16 {%0,%1}, [%2];"
                 : "=r"(r[0]), "=r"(r[1]) : "r"(a));
}
__device__ __forceinline__ void ldsm_x2t(uint32_t* r, uint32_t a) {
    asm volatile("ldmatrix.sync.aligned.m8n8.x2.trans.shared.b16 {%0,%1}, [%2];"
                 : "=r"(r[0]), "=r"(r[1]) : "r"(a));
}
__device__ __forceinline__ uint32_t smem_u32(const void* p) {
    uint32_t a;
    asm("{ .reg .u64 t; cvta.to.shared.u64 t, %1; cvt.u32.u64 %0, t; }" : "=r"(a) : "l"(p));
    return a;
}
__device__ __forceinline__ void cp_async16(uint32_t dst, const void* src) {
    asm volatile("cp.async.cg.shared.global [%0], [%1], 16;" :: "r"(dst), "l"(src));
}
__device__ __forceinline__ void cp_commit() {
    asm volatile("cp.async.commit_group;" ::: "memory");
}
template <int N> __device__ __forceinline__ void cp_wait() {
    asm volatile("cp.async.wait_group %0;" :: "n"(N) : "memory");
}
// pack two fp32 -> bf16x2 (lo = first element)
__device__ __forceinline__ uint32_t cvt_bf16x2(float hi, float lo) {
    uint32_t r;
    asm("cvt.rn.bf16x2.f32 %0, %1, %2;" : "=r"(r) : "f"(hi), "f"(lo));
    return r;
}
__device__ __forceinline__ float un_lo(uint32_t u) { return __uint_as_float(u << 16); }
__device__ __forceinline__ float un_hi(uint32_t u) { return __uint_as_float(u & 0xffff0000u); }

// ---------------------------------------------------------------------------
// fp32 -> bf16 hi/lo split (weights)
// ---------------------------------------------------------------------------
__global__ __launch_bounds__(256) void split_bf16_kernel(
    const float* __restrict__ in, __nv_bfloat16* __restrict__ hi,
    __nv_bfloat16* __restrict__ lo, int n4)
{
    const int i = blockIdx.x * 256 + threadIdx.x;
    if (i >= n4) return;
    float4 v = ((const float4*)in)[i];
    uint32_t h0 = cvt_bf16x2(v.y, v.x);
    uint32_t h1 = cvt_bf16x2(v.w, v.z);
    uint32_t l0 = cvt_bf16x2(v.y - un_hi(h0), v.x - un_lo(h0));
    uint32_t l1 = cvt_bf16x2(v.w - un_hi(h1), v.z - un_lo(h1));
    ((uint2*)hi)[i] = make_uint2(h0, h1);
    ((uint2*)lo)[i] = make_uint2(l0, l1);
}

// ---------------------------------------------------------------------------
// bf16x3 GEMM (mma.sync + ldmatrix + 3-stage cp.async pipeline).
// C[M,N] = A[M,K] @ B[N,K]^T, fp32 accum; C += Ah*Bh + Ah*Bl + Al*Bh.
// Tile 128x128, Kc=64 (128B rows, XOR swizzle), 256 threads / 8 warps
// (warp tile 32x64). Stage = Ah,Al,Bh,Bl x 16KB = 64KB; 3 stages = 192KB.
// ---------------------------------------------------------------------------
#define GEMM_TILE_BYTES 16384
#define GEMM_STAGE_BYTES (4 * GEMM_TILE_BYTES)
#define GEMM_SMEM       (3 * GEMM_STAGE_BYTES + 1024)

__global__ __launch_bounds__(256, 1)
void gemm_bf16x3(const __nv_bfloat16* __restrict__ Ah, const __nv_bfloat16* __restrict__ Al,
                 const __nv_bfloat16* __restrict__ Bh, const __nv_bfloat16* __restrict__ Bl,
                 float* __restrict__ C,
                 __nv_bfloat16* __restrict__ Ch, __nv_bfloat16* __restrict__ Cl,
                 int M, int N, int K)
{
    extern __shared__ char dyn[];
    const int tid  = threadIdx.x;
    const int wid  = tid >> 5;
    const int lane = tid & 31;
    const int wm   = wid >> 1;        // 0..3
    const int wn   = wid & 1;         // 0..1
    const int bm   = blockIdx.y * 128;
    const int bn   = blockIdx.x * 128;

    const uint32_t dyn_u  = smem_u32(dyn);
    const uint32_t tile_u = (dyn_u + 1023u) & ~1023u;

    const int nk   = K >> 6;
    const int grow = tid >> 1;                 // 0..127
    const __nv_bfloat16* pAh = Ah + (size_t)(bm + grow) * K + (tid & 1) * 32;
    const __nv_bfloat16* pAl = Al + (size_t)(bm + grow) * K + (tid & 1) * 32;
    const __nv_bfloat16* pBh = Bh + (size_t)(bn + grow) * K + (tid & 1) * 32;
    const __nv_bfloat16* pBl = Bl + (size_t)(bn + grow) * K + (tid & 1) * 32;

    uint32_t soff[4];
#pragma unroll
    for (int j = 0; j < 4; j++) {
        uint32_t off = (uint32_t)(grow * 128 + (tid & 1) * 64 + j * 16);
        soff[j] = off ^ ((off >> 3) & 0x70u);
    }

    // ldmatrix per-lane addressing constants
    const int lr8   = lane & 7;
    const int rAo   = wm * 32 + lr8 + ((lane >> 3) & 1) * 8;  // + mi*16
    const int kaddA = ((lane >> 4) & 1) * 16;
    // B x4: lanes 0-7 -> (row+0, kb), 8-15 -> (row+0, kb+16),
    //       16-23 -> (row+8, kb), 24-31 -> (row+8, kb+16)
    const uint32_t rB = (uint32_t)((wn * 64 + ((lane >> 4) & 1) * 8 + lr8) * 128);
    const int kselB   = ((lane >> 3) & 1) * 16;

    float acc[2][8][4];
#pragma unroll
    for (int mi = 0; mi < 2; mi++)
#pragma unroll
        for (int j = 0; j < 8; j++)
#pragma unroll
            for (int q = 0; q < 4; q++) acc[mi][j][q] = 0.f;

    auto load_stage = [&](int s, int i) {
        const uint32_t base = tile_u + (uint32_t)s * GEMM_STAGE_BYTES;
        const char* a_h = (const char*)(pAh + (i << 6));
        const char* a_l = (const char*)(pAl + (i << 6));
        const char* b_h = (const char*)(pBh + (i << 6));
        const char* b_l = (const char*)(pBl + (i << 6));
#pragma unroll
        for (int j = 0; j < 4; j++) {
            cp_async16(base + soff[j],                           a_h + j * 16);
            cp_async16(base + GEMM_TILE_BYTES + soff[j],         a_l + j * 16);
            cp_async16(base + 2 * GEMM_TILE_BYTES + soff[j],     b_h + j * 16);
            cp_async16(base + 3 * GEMM_TILE_BYTES + soff[j],     b_l + j * 16);
        }
    };

    load_stage(0, 0); cp_commit();
    load_stage(1, 1); cp_commit();

    int sidx = 0;
    for (int i = 0; i < nk; i++) {
        if (i + 1 < nk) cp_wait<1>(); else cp_wait<0>();
        __syncthreads();
        if (i + 2 < nk) {
            int s2 = sidx + 2; if (s2 >= 3) s2 -= 3;
            load_stage(s2, i + 2);
            cp_commit();
        }

        const uint32_t bu = tile_u + (uint32_t)sidx * GEMM_STAGE_BYTES;
#pragma unroll
        for (int ks = 0; ks < 4; ks++) {
            const int kb = ks * 32;
            const uint32_t swA  = (uint32_t)(kb + kaddA) ^ ((uint32_t)lr8 << 4);
            const uint32_t swB4 = (uint32_t)(kb + kselB) ^ ((uint32_t)lr8 << 4);
            uint32_t ah[2][4], al2[2][4];
#pragma unroll
            for (int mi = 0; mi < 2; mi++) {
                const uint32_t ra = (uint32_t)((rAo + mi * 16) * 128);
                ldsm_x4(ah[mi],  bu + ra + swA);
                ldsm_x4(al2[mi], bu + GEMM_TILE_BYTES + ra + swA);
            }
#pragma unroll
            for (int jj = 0; jj < 4; jj++) {
                const uint32_t rbj = rB + (uint32_t)(jj * 16 * 128);
                uint32_t bh4[4], bl4[4];
                ldsm_x4(bh4, bu + 2 * GEMM_TILE_BYTES + rbj + swB4);
                ldsm_x4(bl4, bu + 3 * GEMM_TILE_BYTES + rbj + swB4);
                // j = 2*jj (frags bh4[0..1]); j = 2*jj+1 (frags bh4[2..3])
                mma_bf16(acc[0][2 * jj],     ah[0],  bh4);
                mma_bf16(acc[1][2 * jj],     ah[1],  bh4);
                mma_bf16(acc[0][2 * jj + 1], ah[0],  bh4 + 2);
                mma_bf16(acc[1][2 * jj + 1], ah[1],  bh4 + 2);
                mma_bf16(acc[0][2 * jj],     ah[0],  bl4);
                mma_bf16(acc[1][2 * jj],     ah[1],  bl4);
                mma_bf16(acc[0][2 * jj + 1], ah[0],  bl4 + 2);
                mma_bf16(acc[1][2 * jj + 1], ah[1],  bl4 + 2);
                mma_bf16(acc[0][2 * jj],     al2[0], bh4);
                mma_bf16(acc[1][2 * jj],     al2[1], bh4);
                mma_bf16(acc[0][2 * jj + 1], al2[0], bh4 + 2);
                mma_bf16(acc[1][2 * jj + 1], al2[1], bh4 + 2);
            }
        }
        __syncthreads();
        if (++sidx == 3) sidx = 0;
    }

    const int lr = lane >> 2;
    if (Ch) {
#pragma unroll
        for (int mi = 0; mi < 2; mi++) {
            const int r0 = bm + wm * 32 + mi * 16 + lr;
#pragma unroll
            for (int j = 0; j < 8; j++) {
                const int col = bn + wn * 64 + j * 8 + ((lane & 3) << 1);
                uint32_t h0 = cvt_bf16x2(acc[mi][j][1], acc[mi][j][0]);
                uint32_t l0 = cvt_bf16x2(acc[mi][j][1] - un_hi(h0), acc[mi][j][0] - un_lo(h0));
                uint32_t h1 = cvt_bf16x2(acc[mi][j][3], acc[mi][j][2]);
                uint32_t l1 = cvt_bf16x2(acc[mi][j][3] - un_hi(h1), acc[mi][j][2] - un_lo(h1));
                *(uint32_t*)(Ch + (size_t)r0 * N + col)       = h0;
                *(uint32_t*)(Cl + (size_t)r0 * N + col)       = l0;
                *(uint32_t*)(Ch + (size_t)(r0 + 8) * N + col) = h1;
                *(uint32_t*)(Cl + (size_t)(r0 + 8) * N + col) = l1;
            }
        }
    } else {
#pragma unroll
        for (int mi = 0; mi < 2; mi++) {
            const int r0 = bm + wm * 32 + mi * 16 + lr;
#pragma unroll
            for (int j = 0; j < 8; j++) {
                const int col = bn + wn * 64 + j * 8 + ((lane & 3) << 1);
                *(float2*)(C + (size_t)r0 * N + col)       = make_float2(acc[mi][j][0], acc[mi][j][1]);
                *(float2*)(C + (size_t)(r0 + 8) * N + col) = make_float2(acc[mi][j][2], acc[mi][j][3]);
            }
        }
    }
}

// ---------------------------------------------------------------------------
// Flash attention, tensor-core bf16x3 (mma.sync + ldmatrix), 2-stage cp.async
// double-buffered K/V. 256 threads / 8 warps; q-tile 128.
// SMEM: Qh,Ql [128][256] (64KB) + 2 stages x (Kh,Kl,Vh,Vl [64][256]) = 192KB.
// ---------------------------------------------------------------------------
#define FL_STAGE_BYTES 65536
#define FL_SMEM (65536 + 2 * FL_STAGE_BYTES)

__global__ __launch_bounds__(256, 1) void flash_bf16_kernel(
    const __nv_bfloat16* __restrict__ Qh_g, const __nv_bfloat16* __restrict__ Ql_g,
    const __nv_bfloat16* __restrict__ Kh_g, const __nv_bfloat16* __restrict__ Kl_g,
    const __nv_bfloat16* __restrict__ Vh_g, const __nv_bfloat16* __restrict__ Vl_g,
    __nv_bfloat16* __restrict__ Oh_g, __nv_bfloat16* __restrict__ Ol_g)
{
    extern __shared__ char sm[];
    char* sQh = sm;
    char* sQl = sm + 32768;
    const uint32_t sm_u = smem_u32(sm);
    const uint32_t uQh = sm_u, uQl = sm_u + 32768;

    const int tid  = threadIdx.x;
    const int wid  = tid >> 5;        // 0..7
    const int lane = tid & 31;
    const int lr   = lane >> 2;
    const int c0   = lane & 3;
    const int q0   = blockIdx.x * 128;
    const int h    = blockIdx.y;
    const int b    = blockIdx.z;
    const size_t rowbase = (size_t)b * SS;
    const float scale = 0.0883883476483184405f;   // 1/sqrt(128)

    // ldmatrix addressing constants
    const int lr8   = lane & 7;
    const int rQ    = wid * 16 + lr8 + ((lane >> 3) & 1) * 8;
    const int kaddA = ((lane >> 4) & 1) * 16;
    const int kaddB = ((lane >> 3) & 1) * 16;
    const int kvro  = lr8 + ((lane >> 3) & 1) * 8;   // + kvks*16 (V trans rows)

    // ---- load Q tile (hi/lo): 128 rows x 256B, swizzled ----
    {
        const char* qh = (const char*)(Qh_g + (rowbase + q0) * DDIM + h * HDIM);
        const char* ql = (const char*)(Ql_g + (rowbase + q0) * DDIM + h * HDIM);
#pragma unroll
        for (int it = 0; it < 8; it++) {
            int li = tid + it * 256;
            int r = li >> 4, c = (li & 15) * 16;
            uint32_t sw = (uint32_t)c ^ (((uint32_t)r & 7u) << 4);
            *(uint4*)(sQh + r * 256 + sw) = *(const uint4*)(qh + (size_t)r * (DDIM * 2) + c);
            *(uint4*)(sQl + r * 256 + sw) = *(const uint4*)(ql + (size_t)r * (DDIM * 2) + c);
        }
    }

    auto load_kv = [&](int s, int t) {
        const uint32_t base = sm_u + 65536u + (uint32_t)s * FL_STAGE_BYTES;
        const char* kh = (const char*)(Kh_g + (rowbase + t * 64) * DDIM + h * HDIM);
        const char* kl = (const char*)(Kl_g + (rowbase + t * 64) * DDIM + h * HDIM);
        const char* vh = (const char*)(Vh_g + (rowbase + t * 64) * DDIM + h * HDIM);
        const char* vl = (const char*)(Vl_g + (rowbase + t * 64) * DDIM + h * HDIM);
#pragma unroll
        for (int it = 0; it < 4; it++) {
            int li = tid + it * 256;
            int r = li >> 4, c = (li & 15) * 16;
            uint32_t sw = (uint32_t)(r * 256) + ((uint32_t)c ^ (((uint32_t)r & 7u) << 4));
            cp_async16(base + sw,          kh + (size_t)r * (DDIM * 2) + c);
            cp_async16(base + 16384 + sw,  kl + (size_t)r * (DDIM * 2) + c);
            cp_async16(base + 32768 + sw,  vh + (size_t)r * (DDIM * 2) + c);
            cp_async16(base + 49152 + sw,  vl + (size_t)r * (DDIM * 2) + c);
        }
    };

    float o[16][4];
#pragma unroll
    for (int j = 0; j < 16; j++)
#pragma unroll
        for (int q = 0; q < 4; q++) o[j][q] = 0.f;
    float m0 = -1e30f, m1 = -1e30f, l0 = 0.f, l1 = 0.f;

    load_kv(0, 0); cp_commit();

    for (int t = 0; t < SS / 64; t++) {
        cp_wait<0>();
        __syncthreads();
        if (t + 1 < SS / 64) { load_kv((t + 1) & 1, t + 1); cp_commit(); }

        const uint32_t sb = sm_u + 65536u + (uint32_t)(t & 1) * FL_STAGE_BYTES;
        const uint32_t uKh = sb, uKl = sb + 16384, uVh = sb + 32768, uVl = sb + 49152;

        // ---- S = Q K^T (bf16x3): warp rows {wid*16+lr, +8}, 64 kv cols ----
        float s[8][4];
#pragma unroll
        for (int j = 0; j < 8; j++)
#pragma unroll
            for (int q = 0; q < 4; q++) s[j][q] = 0.f;

#pragma unroll
        for (int ks = 0; ks < 8; ks++) {
            const int kb = ks * 32;
            const uint32_t swA = (uint32_t)(kb + kaddA) ^ ((uint32_t)lr8 << 4);
            const uint32_t swB = (uint32_t)(kb + kaddB) ^ ((uint32_t)lr8 << 4);
            uint32_t qh4[4], ql4[4];
            ldsm_x4(qh4, uQh + (uint32_t)(rQ * 256) + swA);
            ldsm_x4(ql4, uQl + (uint32_t)(rQ * 256) + swA);
#pragma unroll
            for (int j = 0; j < 8; j++) {
                const uint32_t rb = (uint32_t)((j * 8 + lr8) * 256);
                uint32_t kh2[2], kl2[2];
                ldsm_x2(kh2, uKh + rb + swB);
                ldsm_x2(kl2, uKl + rb + swB);
                mma_bf16(s[j], qh4, kh2);
                mma_bf16(s[j], qh4, kl2);
                mma_bf16(s[j], ql4, kh2);
            }
        }

        // ---- online softmax (rows wid*16+lr and +8) ----
        float mx0 = -1e30f, mx1 = -1e30f;
#pragma unroll
        for (int j = 0; j < 8; j++) {
            s[j][0] *= scale; s[j][1] *= scale; s[j][2] *= scale; s[j][3] *= scale;
            mx0 = fmaxf(mx0, fmaxf(s[j][0], s[j][1]));
            mx1 = fmaxf(mx1, fmaxf(s[j][2], s[j][3]));
        }
        mx0 = fmaxf(mx0, __shfl_xor_sync(0xffffffffu, mx0, 1));
        mx0 = fmaxf(mx0, __shfl_xor_sync(0xffffffffu, mx0, 2));
        mx1 = fmaxf(mx1, __shfl_xor_sync(0xffffffffu, mx1, 1));
        mx1 = fmaxf(mx1, __shfl_xor_sync(0xffffffffu, mx1, 2));
        const float mn0 = fmaxf(m0, mx0), mn1 = fmaxf(m1, mx1);
        const float al0 = __expf(m0 - mn0), al1 = __expf(m1 - mn1);

        uint32_t pah[4][4], pal[4][4];
        float rs0 = 0.f, rs1 = 0.f;
#pragma unroll
        for (int j = 0; j < 8; j++) {
            float p0 = __expf(s[j][0] - mn0);
            float p1 = __expf(s[j][1] - mn0);
            float p2 = __expf(s[j][2] - mn1);
            float p3 = __expf(s[j][3] - mn1);
            rs0 += p0 + p1; rs1 += p2 + p3;
            uint32_t h01 = cvt_bf16x2(p1, p0);
            uint32_t h23 = cvt_bf16x2(p3, p2);
            uint32_t q01 = cvt_bf16x2(p1 - un_hi(h01), p0 - un_lo(h01));
            uint32_t q23 = cvt_bf16x2(p3 - un_hi(h23), p2 - un_lo(h23));
            const int kvks = j >> 1, half = (j & 1) << 1;
            pah[kvks][half]     = h01;
            pah[kvks][half + 1] = h23;
            pal[kvks][half]     = q01;
            pal[kvks][half + 1] = q23;
        }
        rs0 += __shfl_xor_sync(0xffffffffu, rs0, 1);
        rs0 += __shfl_xor_sync(0xffffffffu, rs0, 2);
        rs1 += __shfl_xor_sync(0xffffffffu, rs1, 1);
        rs1 += __shfl_xor_sync(0xffffffffu, rs1, 2);
        l0 = l0 * al0 + rs0;
        l1 = l1 * al1 + rs1;
        m0 = mn0; m1 = mn1;
#pragma unroll
        for (int jn = 0; jn < 16; jn++) {
            o[jn][0] *= al0; o[jn][1] *= al0;
            o[jn][2] *= al1; o[jn][3] *= al1;
        }

        // ---- O += P V (bf16x3); V fragments via ldmatrix.trans ----
#pragma unroll
        for (int kvks = 0; kvks < 4; kvks++) {
            const uint32_t* pa = pah[kvks];
            const uint32_t* pl = pal[kvks];
            const uint32_t kvr = (uint32_t)((kvks * 16 + kvro) * 256);
            const uint32_t swr = ((uint32_t)lr8 << 4);
#pragma unroll
            for (int jn = 0; jn < 16; jn++) {
                const uint32_t swV = ((uint32_t)(jn * 16)) ^ swr;
                uint32_t vh2[2], vl2[2];
                ldsm_x2t(vh2, uVh + kvr + swV);
                ldsm_x2t(vl2, uVl + kvr + swV);
                mma_bf16(o[jn], pa, vh2);
                mma_bf16(o[jn], pa, vl2);
                mma_bf16(o[jn], pl, vh2);
            }
        }
    }

    // ---- normalize and store att as bf16 hi/lo ----
    const float i0 = 1.f / l0, i1 = 1.f / l1;
    const size_t rg0 = rowbase + q0 + wid * 16 + lr;
    const int colb = h * HDIM + (c0 << 1);
#pragma unroll
    for (int jn = 0; jn < 16; jn++) {
        float v0 = o[jn][0] * i0, v1 = o[jn][1] * i0;
        float v2 = o[jn][2] * i1, v3 = o[jn][3] * i1;
        uint32_t h01 = cvt_bf16x2(v1, v0);
        uint32_t l01 = cvt_bf16x2(v1 - un_hi(h01), v0 - un_lo(h01));
        uint32_t h23 = cvt_bf16x2(v3, v2);
        uint32_t l23 = cvt_bf16x2(v3 - un_hi(h23), v2 - un_lo(h23));
        const size_t off0 = rg0 * DDIM + colb + jn * 8;
        const size_t off1 = (rg0 + 8) * DDIM + colb + jn * 8;
        *(uint32_t*)(Oh_g + off0) = h01;
        *(uint32_t*)(Ol_g + off0) = l01;
        *(uint32_t*)(Oh_g + off1) = h23;
        *(uint32_t*)(Ol_g + off1) = l23;
    }
}

// ---------------------------------------------------------------------------
// RMSNorm with fused bf16 hi/lo split output
// ---------------------------------------------------------------------------
__global__ __launch_bounds__(256) void rmsnorm_split_kernel(
    const float* __restrict__ in, const float* __restrict__ w,
    __nv_bfloat16* __restrict__ oh, __nv_bfloat16* __restrict__ ol)
{
    const int row  = blockIdx.x;
    const int base = threadIdx.x * 8;
    const float* r = in + (size_t)row * DDIM;

    float v[8];
    *(float4*)(v)     = *(const float4*)(r + base);
    *(float4*)(v + 4) = *(const float4*)(r + base + 4);

    float ss = 0.f;
#pragma unroll
    for (int i = 0; i < 8; i++) ss += v[i] * v[i];
#pragma unroll
    for (int o = 16; o > 0; o >>= 1) ss += __shfl_xor_sync(0xffffffffu, ss, o);

    __shared__ float red[8];
    __shared__ float sscale;
    if ((threadIdx.x & 31) == 0) red[threadIdx.x >> 5] = ss;
    __syncthreads();
    if (threadIdx.x == 0) {
        float t = 0.f;
#pragma unroll
        for (int i = 0; i < 8; i++) t += red[i];
        sscale = rsqrtf(t / (float)DDIM + EPSV);
    }
    __syncthreads();
    const float sc = sscale;

    uint32_t hh[4], ll[4];
#pragma unroll
    for (int p = 0; p < 4; p++) {
        float f0 = v[2 * p]     * sc * w[base + 2 * p];
        float f1 = v[2 * p + 1] * sc * w[base + 2 * p + 1];
        hh[p] = cvt_bf16x2(f1, f0);
        ll[p] = cvt_bf16x2(f1 - un_hi(hh[p]), f0 - un_lo(hh[p]));
    }
    *(uint4*)(oh + (size_t)row * DDIM + base) = make_uint4(hh[0], hh[1], hh[2], hh[3]);
    *(uint4*)(ol + (size_t)row * DDIM + base) = make_uint4(ll[0], ll[1], ll[2], ll[3]);
}

// ---------------------------------------------------------------------------
// RMSNorm of (ff + residual) -> final fp32 output
// ---------------------------------------------------------------------------
__global__ __launch_bounds__(256) void rms_resid_out_kernel(
    const float* __restrict__ ff, const float* __restrict__ res,
    const float* __restrict__ w, float* __restrict__ out)
{
    const int row  = blockIdx.x;
    const int base = threadIdx.x * 8;
    const float* f = ff  + (size_t)row * DDIM;
    const float* r = res + (size_t)row * DDIM;

    float4 a0 = *(const float4*)(f + base);
    float4 a1 = *(const float4*)(f + base + 4);
    float4 b0 = *(const float4*)(r + base);
    float4 b1 = *(const float4*)(r + base + 4);

    float v[8];
    v[0] = a0.x + b0.x; v[1] = a0.y + b0.y; v[2] = a0.z + b0.z; v[3] = a0.w + b0.w;
    v[4] = a1.x + b1.x; v[5] = a1.y + b1.y; v[6] = a1.z + b1.z; v[7] = a1.w + b1.w;

    float ss = 0.f;
#pragma unroll
    for (int i = 0; i < 8; i++) ss += v[i] * v[i];
#pragma unroll
    for (int o = 16; o > 0; o >>= 1) ss += __shfl_xor_sync(0xffffffffu, ss, o);

    __shared__ float red[8];
    __shared__ float sscale;
    if ((threadIdx.x & 31) == 0) red[threadIdx.x >> 5] = ss;
    __syncthreads();
    if (threadIdx.x == 0) {
        float t = 0.f;
#pragma unroll
        for (int i = 0; i < 8; i++) t += red[i];
        sscale = rsqrtf(t / (float)DDIM + EPSV);
    }
    __syncthreads();
    const float sc = sscale;

    float o8[8];
#pragma unroll
    for (int i = 0; i < 8; i++) o8[i] = v[i] * sc * w[base + i];
    float* op = out + (size_t)row * DDIM + base;
    *(float4*)(op)     = *(float4*)(o8);
    *(float4*)(op + 4) = *(float4*)(o8 + 4);
}

// ---------------------------------------------------------------------------
// SiLU-mul with fused bf16 hi/lo split output: hs = silu(h1) * h3
// ---------------------------------------------------------------------------
__global__ __launch_bounds__(256) void silu_mul_split_kernel(
    const float* __restrict__ h1, const float* __restrict__ h3,
    __nv_bfloat16* __restrict__ oh, __nv_bfloat16* __restrict__ ol, int n4)
{
    const int i = blockIdx.x * 256 + threadIdx.x;
    if (i >= n4) return;
    float4 a = ((const float4*)h1)[i];
    float4 b = ((const float4*)h3)[i];
    float r0 = a.x * (1.f / (1.f + __expf(-a.x))) * b.x;
    float r1 = a.y * (1.f / (1.f + __expf(-a.y))) * b.y;
    float r2 = a.z * (1.f / (1.f + __expf(-a.z))) * b.z;
    float r3 = a.w * (1.f / (1.f + __expf(-a.w))) * b.w;
    uint32_t h0 = cvt_bf16x2(r1, r0);
    uint32_t h1u = cvt_bf16x2(r3, r2);
    uint32_t l0 = cvt_bf16x2(r1 - un_hi(h0), r0 - un_lo(h0));
    uint32_t l1 = cvt_bf16x2(r3 - un_hi(h1u), r2 - un_lo(h1u));
    ((uint2*)oh)[i] = make_uint2(h0, h1u);
    ((uint2*)ol)[i] = make_uint2(l0, l1);
}

// ---------------------------------------------------------------------------
// Host orchestration
// ---------------------------------------------------------------------------
extern "C" void kernel_launch(void* const* d_in, const int* in_sizes, int n_in,
                              void* d_out, int out_size)
{
    (void)in_sizes; (void)n_in; (void)out_size;

    const float* x           = (const float*)d_in[0];
    const float* y           = (const float*)d_in[1];
    const float* attn_norm_w = (const float*)d_in[2];
    const float* wq[2]  = {(const float*)d_in[3],  (const float*)d_in[7]};
    const float* wk[2]  = {(const float*)d_in[4],  (const float*)d_in[8]};
    const float* wv[2]  = {(const float*)d_in[5],  (const float*)d_in[9]};
    const float* wo[2]  = {(const float*)d_in[6],  (const float*)d_in[10]};
    const float* w1[2]  = {(const float*)d_in[11], (const float*)d_in[15]};
    const float* w2[2]  = {(const float*)d_in[12], (const float*)d_in[16]};
    const float* w3[2]  = {(const float*)d_in[13], (const float*)d_in[17]};
    const float* fnw[2] = {(const float*)d_in[14], (const float*)d_in[18]};
    float* out = (float*)d_out;

    float *h1, *h3, *ff;
    cudaGetSymbolAddress((void**)&h1, g_h1);
    cudaGetSymbolAddress((void**)&h3, g_h3);
    cudaGetSymbolAddress((void**)&ff, g_ff);

    __nv_bfloat16 *xnh, *xnl, *ynh, *ynl, *qh, *ql, *kh, *kl, *vh, *vl;
    __nv_bfloat16 *ath, *atl, *prh, *prl, *hsh, *hsl, *wh, *wl;
    cudaGetSymbolAddress((void**)&xnh, g_xn_h); cudaGetSymbolAddress((void**)&xnl, g_xn_l);
    cudaGetSymbolAddress((void**)&ynh, g_yn_h); cudaGetSymbolAddress((void**)&ynl, g_yn_l);
    cudaGetSymbolAddress((void**)&qh,  g_q_h);  cudaGetSymbolAddress((void**)&ql,  g_q_l);
    cudaGetSymbolAddress((void**)&kh,  g_k_h);  cudaGetSymbolAddress((void**)&kl,  g_k_l);
    cudaGetSymbolAddress((void**)&vh,  g_v_h);  cudaGetSymbolAddress((void**)&vl,  g_v_l);
    cudaGetSymbolAddress((void**)&ath, g_att_h); cudaGetSymbolAddress((void**)&atl, g_att_l);
    cudaGetSymbolAddress((void**)&prh, g_pr_h); cudaGetSymbolAddress((void**)&prl, g_pr_l);
    cudaGetSymbolAddress((void**)&hsh, g_hs_h); cudaGetSymbolAddress((void**)&hsl, g_hs_l);
    cudaGetSymbolAddress((void**)&wh,  g_w_h);  cudaGetSymbolAddress((void**)&wl,  g_w_l);

    cudaFuncSetAttribute(gemm_bf16x3,
                         cudaFuncAttributeMaxDynamicSharedMemorySize, GEMM_SMEM);
    cudaFuncSetAttribute(flash_bf16_kernel,
                         cudaFuncAttributeMaxDynamicSharedMemorySize, FL_SMEM);

    // Pre-norms with fused hi/lo split
    rmsnorm_split_kernel<<<BSR, 256>>>(x, attn_norm_w, xnh, xnl);
    rmsnorm_split_kernel<<<BSR, 256>>>(y, attn_norm_w, ynh, ynl);

    const dim3 gAttn(SS / 128, HH, BB);
    const int  n4ff = BSR * FFD / 4;

    auto splitw = [&](const float* src, int n) {
        int n4s = n / 4;
        split_bf16_kernel<<<(n4s + 255) / 256, 256>>>(src, wh, wl, n4s);
    };
    auto gemm_s = [&](const __nv_bfloat16* Ah_, const __nv_bfloat16* Al_,
                      __nv_bfloat16* Ch_, __nv_bfloat16* Cl_, int M, int N, int K) {
        dim3 g(N / 128, M / 128);
        gemm_bf16x3<<<g, 256, GEMM_SMEM>>>(Ah_, Al_, wh, wl, nullptr, Ch_, Cl_, M, N, K);
    };
    auto gemm_f = [&](const __nv_bfloat16* Ah_, const __nv_bfloat16* Al_,
                      float* C_, int M, int N, int K) {
        dim3 g(N / 128, M / 128);
        gemm_bf16x3<<<g, 256, GEMM_SMEM>>>(Ah_, Al_, wh, wl, C_, nullptr, nullptr, M, N, K);
    };

    for (int p = 0; p < 2; p++) {
        const __nv_bfloat16* qih = (p == 0) ? xnh : ynh;
        const __nv_bfloat16* qil = (p == 0) ? xnl : ynl;
        const __nv_bfloat16* kih = (p == 0) ? ynh : xnh;
        const __nv_bfloat16* kil = (p == 0) ? ynl : xnl;
        const float* resid = (p == 0) ? x : y;

        splitw(wq[p], DDIM * DDIM);  gemm_s(qih, qil, qh, ql, BSR, DDIM, DDIM);
        splitw(wk[p], DDIM * DDIM);  gemm_s(kih, kil, kh, kl, BSR, DDIM, DDIM);
        splitw(wv[p], DDIM * DDIM);  gemm_s(kih, kil, vh, vl, BSR, DDIM, DDIM);

        flash_bf16_kernel<<<gAttn, 256, FL_SMEM>>>(qh, ql, kh, kl, vh, vl, ath, atl);

        splitw(wo[p], DDIM * DDIM);  gemm_s(ath, atl, prh, prl, BSR, DDIM, DDIM);

        splitw(w1[p], FFD * DDIM);   gemm_f(prh, prl, h1, BSR, FFD, DDIM);
        splitw(w3[p], FFD * DDIM);   gemm_f(prh, prl, h3, BSR, FFD, DDIM);

        silu_mul_split_kernel<<<(n4ff + 255) / 256, 256>>>(h1, h3, hsh, hsl, n4ff);

        splitw(w2[p], DDIM * FFD);   gemm_f(hsh, hsl, ff, BSR, DDIM, FFD);

        rms_resid_out_kernel<<<BSR, 256>>>(ff, resid, fnw[p],
                                           out + (size_t)p * BSR * DDIM);
    }
}